// round 6
// baseline (speedup 1.0000x reference)
#include <cuda_runtime.h>
#include <math.h>

// ---------------------------------------------------------------------------
// Problem constants
// ---------------------------------------------------------------------------
constexpr int B_ = 16;
constexpr int H_ = 512;
constexpr int W_ = 512;
constexpr int NPIX = H_ * W_;          // 262144 = 2^18
constexpr int NB = B_ * NPIX;          // 4194304
constexpr int NTILES = B_ * 256;       // 4096 hysteresis tiles (32x32)

// ---------------------------------------------------------------------------
// Scratch
// ---------------------------------------------------------------------------
__device__ float g_gray[NB];
__device__ float g_t0[NB];
__device__ float g_t1[NB];
__device__ float g_mag[NB];
__device__ unsigned char g_q[NB];
__device__ unsigned char g_edge[NB];
__device__ unsigned char g_weak[NB];
__device__ float g_comb[NB];
__device__ float g_h1[16 * NB];
__device__ float g_h2[16 * NB];
__device__ float g_h3[8 * NB];
__device__ float g_deep[NB];
__device__ float g_ce[2 * NB];
__device__ float g_r1[8 * NB];
__device__ float g_r2[4 * NB];
__device__ float g_refined[NB];
__device__ int g_flags[2];
__device__ int g_barcnt;
__device__ int g_barphase;
__device__ unsigned char g_dirty[2][NTILES];

struct K5 { float k[5]; };

// ---------------------------------------------------------------------------
// f32x2 packed helpers (sm_100+)
// ---------------------------------------------------------------------------
typedef unsigned long long ull;
__device__ __forceinline__ ull pk2(float lo, float hi) {
    ull r; asm("mov.b64 %0, {%1, %2};" : "=l"(r) : "f"(lo), "f"(hi)); return r;
}
__device__ __forceinline__ void upk2(ull v, float& lo, float& hi) {
    asm("mov.b64 {%0, %1}, %2;" : "=f"(lo), "=f"(hi) : "l"(v));
}
__device__ __forceinline__ ull fma2(ull a, ull b, ull c) {
    ull d; asm("fma.rn.f32x2 %0, %1, %2, %3;" : "=l"(d) : "l"(a), "l"(b), "l"(c)); return d;
}

// ---------------------------------------------------------------------------
// Canny-path arithmetic: FROZEN. Separate IEEE fmul/fadd chains (no fma),
// row-major taps, acc from 0, zero taps skipped, double atan2 rounded once.
// Do not modify — bit-exactness of combined_canny depends on it.
// ---------------------------------------------------------------------------
__global__ void __launch_bounds__(256) gray_kernel(const float* __restrict__ x,
                                                   float* __restrict__ gray) {
    int idx = blockIdx.x * 256 + threadIdx.x;
    if (idx >= NB) return;
    int b = idx >> 18;
    int p = idx & (NPIX - 1);
    const float* xb = x + (size_t)b * 3 * NPIX;
    float t0 = __fmul_rn(0.299f, xb[p]);
    float t1 = __fmul_rn(0.587f, xb[NPIX + p]);
    float t2 = __fmul_rn(0.114f, xb[2 * NPIX + p]);
    gray[idx] = __fadd_rn(__fadd_rn(t0, t1), t2);
}

__global__ void __launch_bounds__(256) blur_v_kernel(const float* __restrict__ in,
                                                     float* __restrict__ out, K5 kk) {
    int idx = blockIdx.x * 256 + threadIdx.x;
    if (idx >= NB) return;
    int p = idx & (NPIX - 1);
    int y = p >> 9;
    int x = p & 511;
    const float* ib = in + (idx - p);
    float s = 0.f;
#pragma unroll
    for (int i = 0; i < 5; i++) {
        int yy = y + i - 2;
        if ((unsigned)yy < (unsigned)H_)
            s = __fadd_rn(s, __fmul_rn(kk.k[i], ib[yy * W_ + x]));
    }
    out[idx] = s;
}

__global__ void __launch_bounds__(256) blur_h_kernel(const float* __restrict__ in,
                                                     float* __restrict__ out, K5 kk) {
    int idx = blockIdx.x * 256 + threadIdx.x;
    if (idx >= NB) return;
    int p = idx & (NPIX - 1);
    int x = p & 511;
    const float* ib = in + (idx - x);
    float s = 0.f;
#pragma unroll
    for (int i = 0; i < 5; i++) {
        int xx = x + i - 2;
        if ((unsigned)xx < (unsigned)W_)
            s = __fadd_rn(s, __fmul_rn(kk.k[i], ib[xx]));
    }
    out[idx] = s;
}

__global__ void __launch_bounds__(256) magq_kernel(const float* __restrict__ in,
                                                   float* __restrict__ mag,
                                                   unsigned char* __restrict__ q) {
    int idx = blockIdx.x * 256 + threadIdx.x;
    if (idx >= NB) return;
    int p = idx & (NPIX - 1);
    int y = p >> 9;
    int x = p & 511;
    const float* ib = in + (idx - p);
    float a[3][3];
#pragma unroll
    for (int dy = 0; dy < 3; dy++)
#pragma unroll
        for (int dx = 0; dx < 3; dx++) {
            int yy = y + dy - 1, xx = x + dx - 1;
            float v = 0.f;
            if ((unsigned)yy < (unsigned)H_ && (unsigned)xx < (unsigned)W_)
                v = ib[yy * W_ + xx];
            a[dy][dx] = v;
        }
    float gx = 0.f;
    gx = __fadd_rn(gx, __fmul_rn(-1.f, a[0][0]));
    gx = __fadd_rn(gx, __fmul_rn( 1.f, a[0][2]));
    gx = __fadd_rn(gx, __fmul_rn(-2.f, a[1][0]));
    gx = __fadd_rn(gx, __fmul_rn( 2.f, a[1][2]));
    gx = __fadd_rn(gx, __fmul_rn(-1.f, a[2][0]));
    gx = __fadd_rn(gx, __fmul_rn( 1.f, a[2][2]));
    float gy = 0.f;
    gy = __fadd_rn(gy, __fmul_rn(-1.f, a[0][0]));
    gy = __fadd_rn(gy, __fmul_rn(-2.f, a[0][1]));
    gy = __fadd_rn(gy, __fmul_rn(-1.f, a[0][2]));
    gy = __fadd_rn(gy, __fmul_rn( 1.f, a[2][0]));
    gy = __fadd_rn(gy, __fmul_rn( 2.f, a[2][1]));
    gy = __fadd_rn(gy, __fmul_rn( 1.f, a[2][2]));
    float m = sqrtf(__fadd_rn(__fadd_rn(__fmul_rn(gx, gx), __fmul_rn(gy, gy)), 1e-12f));
    float ang = (float)atan2((double)gy, (double)gx);
    const float pi4 = 0.78539816339744830962f;
    int qi = (int)rintf(__fdiv_rn(ang, pi4));
    qi = ((qi % 4) + 4) % 4;
    mag[idx] = m;
    q[idx] = (unsigned char)qi;
}

__global__ void __launch_bounds__(256) nms_kernel(const float* __restrict__ mag,
                                                  const unsigned char* __restrict__ q,
                                                  unsigned char* __restrict__ edge,
                                                  unsigned char* __restrict__ weak) {
    int idx = blockIdx.x * 256 + threadIdx.x;
    if (idx >= NB) return;
    int p = idx & (NPIX - 1);
    int y = p >> 9;
    int x = p & 511;
    const float* mb = mag + (idx - p);
    float m = mag[idx];
    int qq = q[idx];
    int day, dax, dby, dbx;
    if (qq == 0)      { day = 0;  dax = 1;  dby = 0;  dbx = -1; }
    else if (qq == 1) { day = -1; dax = 1;  dby = 1;  dbx = -1; }
    else if (qq == 2) { day = -1; dax = 0;  dby = 1;  dbx = 0;  }
    else              { day = -1; dax = -1; dby = 1;  dbx = 1;  }
    float na = 0.f, nb = 0.f;
    {
        int yy = y + day, xx = x + dax;
        if ((unsigned)yy < (unsigned)H_ && (unsigned)xx < (unsigned)W_) na = mb[yy * W_ + xx];
        yy = y + dby; xx = x + dbx;
        if ((unsigned)yy < (unsigned)H_ && (unsigned)xx < (unsigned)W_) nb = mb[yy * W_ + xx];
    }
    float nmsv = (m >= na && m >= nb) ? m : 0.f;
    edge[idx] = (nmsv > 0.2f) ? 1 : 0;
    weak[idx] = (nmsv > 0.1f && nmsv <= 0.2f) ? 1 : 0;
}

__global__ void __launch_bounds__(256) combine_kernel(const unsigned char* __restrict__ e,
                                                      float* __restrict__ comb, int first) {
    int idx = blockIdx.x * 256 + threadIdx.x;
    if (idx >= NB) return;
    float v = (float)e[idx];
    comb[idx] = first ? v : fmaxf(comb[idx], v);
}

__global__ void __launch_bounds__(256) init_sync_kernel() {
    int i = blockIdx.x * 256 + threadIdx.x;
    if (i == 0) {
        g_flags[0] = 0;
        g_flags[1] = 0;
        g_barcnt = 0;
        g_barphase = 0;
    }
    if (i < NTILES) {
        g_dirty[0][i] = 1;
        g_dirty[1][i] = 0;
    }
}

// ---------------------------------------------------------------------------
// Persistent hysteresis kernel with dirty-tile frontier.
// Fixpoint is unique & monotone -> any schedule yields the same answer.
// ---------------------------------------------------------------------------
__device__ __forceinline__ void grid_barrier(int* phase) {
    __syncthreads();
    if (threadIdx.x == 0 && threadIdx.y == 0) {
        __threadfence();
        int target = *phase + 1;
        if (atomicAdd(&g_barcnt, 1) == (int)gridDim.x - 1) {
            g_barcnt = 0;
            __threadfence();
            atomicExch(&g_barphase, target);
        } else {
            while (atomicAdd(&g_barphase, 0) < target) { __nanosleep(64); }
        }
        __threadfence();
        *phase = target;
    }
    __syncthreads();
}

__global__ void __launch_bounds__(256) hysteresis_kernel(int ntiles) {
    __shared__ unsigned char se[34][34];
    __shared__ unsigned char sw[32][32];
    const int tid = threadIdx.y * 32 + threadIdx.x;
    int phase = 0;
    for (int it = 0;; it++) {
        const int cur = it & 1, nxt = (it + 1) & 1;
        if (blockIdx.x == 0 && tid == 0) {
            ((volatile int*)g_flags)[nxt] = 0;
        }
        int any = 0;
        for (int t = blockIdx.x; t < ntiles; t += gridDim.x) {
            if (!((volatile unsigned char*)g_dirty[cur])[t]) continue;
            __syncthreads();  // protect smem reuse across tiles
            if (tid == 0) g_dirty[cur][t] = 0;
            int b = t >> 8;
            int ti = t & 255;
            int ty = ti >> 4, tx = ti & 15;
            int ty0 = ty << 5, tx0 = tx << 5;
            const size_t base = (size_t)b << 18;
            for (int i = tid; i < 34 * 34; i += 256) {
                int r = i / 34, c = i % 34;
                int y = ty0 + r - 1, x = tx0 + c - 1;
                unsigned char v = 0;
                if ((unsigned)y < (unsigned)H_ && (unsigned)x < (unsigned)W_)
                    v = g_edge[base + ((size_t)y << 9) + x];
                se[r][c] = v;
            }
            bool myneed = false;
#pragma unroll
            for (int k2 = 0; k2 < 4; k2++) {
                int r = threadIdx.y + 8 * k2;
                int y = ty0 + r, x = tx0 + threadIdx.x;
                unsigned char wv = g_weak[base + ((size_t)y << 9) + x];
                sw[r][threadIdx.x] = wv;
                if (wv) myneed = true;
            }
            if (!__syncthreads_or(myneed ? 1 : 0)) continue;
            bool tilechanged = false;
            for (;;) {
                bool ch = false;
#pragma unroll
                for (int k2 = 0; k2 < 4; k2++) {
                    int r = threadIdx.y + 8 * k2;
                    int c = threadIdx.x;
                    if (sw[r][c] && !se[r + 1][c + 1]) {
                        int n = se[r][c] | se[r][c + 1] | se[r][c + 2]
                              | se[r + 1][c] | se[r + 1][c + 2]
                              | se[r + 2][c] | se[r + 2][c + 1] | se[r + 2][c + 2];
                        if (n) { se[r + 1][c + 1] = 1; ch = true; }
                    }
                }
                if (__syncthreads_or(ch ? 1 : 0)) tilechanged = true;
                else break;
            }
            if (tilechanged) {
                any = 1;
#pragma unroll
                for (int k2 = 0; k2 < 4; k2++) {
                    int r = threadIdx.y + 8 * k2;
                    int y = ty0 + r, x = tx0 + threadIdx.x;
                    g_edge[base + ((size_t)y << 9) + x] = se[r + 1][threadIdx.x + 1];
                }
                if (tid == 0) {
                    // mark 8 neighbors (same image) for the next sweep
                    for (int dy = -1; dy <= 1; dy++)
                        for (int dx = -1; dx <= 1; dx++) {
                            if (dy == 0 && dx == 0) continue;
                            int ny = ty + dy, nx = tx + dx;
                            if ((unsigned)ny < 16u && (unsigned)nx < 16u)
                                g_dirty[nxt][(t & ~255) | (ny << 4) | nx] = 1;
                        }
                }
            }
        }
        if (any && tid == 0) ((volatile int*)g_flags)[cur] = 1;
        grid_barrier(&phase);
        int f = ((volatile int*)g_flags)[cur];
        grid_barrier(&phase);
        if (!f) break;
    }
}

// ---------------------------------------------------------------------------
// Conv v2: 3x3 SAME, 32x32 tile, 256 threads, 4 px/thread (column of 4 rows),
// packed f32x2 accumulation, vectorized broadcast weights. ACT: 0=lrelu 1=sigmoid
// ---------------------------------------------------------------------------
template <int CIN, int COUT, int ACT>
__global__ void __launch_bounds__(256) conv3x3_v2(const float* __restrict__ in,
                                                  const float* __restrict__ wt,
                                                  const float* __restrict__ bias,
                                                  float* __restrict__ out) {
    extern __shared__ float smem[];
    float* s_in = smem;                          // [CIN][34][34]
    float* s_w  = smem + CIN * 34 * 34;          // [CIN][COUT][12] (9 used, padded)
    const int tid = threadIdx.x;
    const int lx = tid & 31, ly = tid >> 5;      // ly 0..7
    const int b  = blockIdx.z;
    const int x0 = blockIdx.x * 32, y0 = blockIdx.y * 32;

    for (int i = tid; i < CIN * COUT * 12; i += 256) {
        int t  = i % 12;
        int co = (i / 12) % COUT;
        int ci = i / (12 * COUT);
        s_w[i] = (t < 9) ? wt[(co * CIN + ci) * 9 + t] : 0.f;
    }
    const float* inb = in + (size_t)b * CIN * NPIX;
    for (int i = tid; i < CIN * 34 * 34; i += 256) {
        int c  = i / (34 * 34);
        int r  = (i / 34) % 34;
        int cc = i % 34;
        int y = y0 + r - 1, x = x0 + cc - 1;
        float v = 0.f;
        if ((unsigned)y < (unsigned)H_ && (unsigned)x < (unsigned)W_)
            v = inb[(size_t)c * NPIX + y * W_ + x];
        s_in[i] = v;
    }
    __syncthreads();

    ull accA[COUT], accB[COUT];
#pragma unroll
    for (int co = 0; co < COUT; co++) {
        float bv = bias[co];
        accA[co] = pk2(bv, bv);
        accB[co] = pk2(bv, bv);
    }
    const int ybase = ly * 4;   // first output row (local)
#pragma unroll
    for (int ci = 0; ci < CIN; ci++) {
        const float* sc = s_in + ci * (34 * 34);
        float r6[6][3];
#pragma unroll
        for (int dy = 0; dy < 6; dy++)
#pragma unroll
            for (int dx = 0; dx < 3; dx++)
                r6[dy][dx] = sc[(ybase + dy) * 34 + lx + dx];
        ull vA[9], vB[9];
#pragma unroll
        for (int t = 0; t < 9; t++) {
            int dy = t / 3, dx = t % 3;
            vA[t] = pk2(r6[dy][dx],     r6[dy + 1][dx]);
            vB[t] = pk2(r6[dy + 2][dx], r6[dy + 3][dx]);
        }
#pragma unroll
        for (int co = 0; co < COUT; co++) {
            const float4* wp = reinterpret_cast<const float4*>(&s_w[(ci * COUT + co) * 12]);
            float4 w0 = wp[0], w1 = wp[1], w2 = wp[2];
            float w[9] = {w0.x, w0.y, w0.z, w0.w, w1.x, w1.y, w1.z, w1.w, w2.x};
#pragma unroll
            for (int t = 0; t < 9; t++) {
                ull ww = pk2(w[t], w[t]);
                accA[co] = fma2(vA[t], ww, accA[co]);
                accB[co] = fma2(vB[t], ww, accB[co]);
            }
        }
    }
    float* ob = out + (size_t)b * COUT * NPIX + (y0 + ybase) * W_ + (x0 + lx);
#pragma unroll
    for (int co = 0; co < COUT; co++) {
        float p0, p1, p2, p3;
        upk2(accA[co], p0, p1);
        upk2(accB[co], p2, p3);
        float pv[4] = {p0, p1, p2, p3};
#pragma unroll
        for (int r = 0; r < 4; r++) {
            float v = pv[r];
            if (ACT == 0) v = (v >= 0.f) ? v : 0.2f * v;
            else v = 1.f / (1.f + expf(-v));
            ob[(size_t)co * NPIX + r * W_] = v;
        }
    }
}

__global__ void __launch_bounds__(256) pack_ce_kernel(const float* __restrict__ comb,
                                                      const float* __restrict__ deep,
                                                      float* __restrict__ ce) {
    int idx = blockIdx.x * 256 + threadIdx.x;
    if (idx >= NB) return;
    int b = idx >> 18;
    int p = idx & (NPIX - 1);
    float* cb = ce + (size_t)b * 2 * NPIX;
    cb[p] = comb[idx];
    cb[NPIX + p] = deep[idx];
}

__global__ void __launch_bounds__(256) final_kernel(const float* __restrict__ refined,
                                                    const float* __restrict__ deep,
                                                    const float* __restrict__ comb,
                                                    const float* __restrict__ mask,
                                                    float* __restrict__ out) {
    int idx = blockIdx.x * 256 + threadIdx.x;
    if (idx >= NB) return;
    int b = idx >> 18;
    int p = idx & (NPIX - 1);
    float r = refined[idx];
    float d = deep[idx];
    float m = mask[idx];
    float c = comb[idx];
    float em = __fadd_rn(__fmul_rn(r, __fadd_rn(1.f, -m)),
                         __fmul_rn(__fmul_rn(d, m), 0.5f));
    const size_t T = (size_t)NB;
    out[idx] = em;
    float* ef = out + T + (size_t)b * 2 * NPIX;
    ef[p] = em;
    ef[NPIX + p] = d;
    out[3 * T + idx] = c;
    out[4 * T + idx] = d;
}

// ---------------------------------------------------------------------------
// Host side
// ---------------------------------------------------------------------------
static void gauss5(float sigma, float* k) {
    float kk[5];
    for (int i = 0; i < 5; i++) {
        float r = (float)i - 2.0f;
        float rr = r * r;
        float denom = (float)(2.0 * (double)sigma * (double)sigma);
        float arg = -(rr / denom);
        kk[i] = (float)exp((double)arg);
    }
    float sum = ((((kk[0] + kk[1]) + kk[2]) + kk[3]) + kk[4]);
    for (int i = 0; i < 5; i++) k[i] = kk[i] / sum;
}

template <int CIN, int COUT, int ACT>
static void launch_conv(const float* in, const float* wt, const float* bias, float* out) {
    int smem = (CIN * 34 * 34 + CIN * COUT * 12) * (int)sizeof(float);
    if (smem > 48 * 1024) {
        cudaFuncSetAttribute(conv3x3_v2<CIN, COUT, ACT>,
                             cudaFuncAttributeMaxDynamicSharedMemorySize, smem);
    }
    dim3 grid(W_ / 32, H_ / 32, B_);
    conv3x3_v2<CIN, COUT, ACT><<<grid, 256, smem>>>(in, wt, bias, out);
}

extern "C" void kernel_launch(void* const* d_in, const int* in_sizes, int n_in,
                              void* d_out, int out_size) {
    const float* x    = (const float*)d_in[0];
    const float* mask = (const float*)d_in[1];
    const float* wd1 = (const float*)d_in[2];
    const float* bd1 = (const float*)d_in[3];
    const float* wd2 = (const float*)d_in[4];
    const float* bd2 = (const float*)d_in[5];
    const float* wd3 = (const float*)d_in[6];
    const float* bd3 = (const float*)d_in[7];
    const float* wd4 = (const float*)d_in[8];
    const float* bd4 = (const float*)d_in[9];
    const float* wr1 = (const float*)d_in[10];
    const float* br1 = (const float*)d_in[11];
    const float* wr2 = (const float*)d_in[12];
    const float* br2 = (const float*)d_in[13];
    const float* wr3 = (const float*)d_in[14];
    const float* br3 = (const float*)d_in[15];
    float* out = (float*)d_out;

    float *p_gray, *p_t0, *p_t1, *p_mag, *p_comb, *p_h1, *p_h2, *p_h3;
    float *p_deep, *p_ce, *p_r1, *p_r2, *p_refined;
    unsigned char *p_q, *p_e, *p_w;
    cudaGetSymbolAddress((void**)&p_gray, g_gray);
    cudaGetSymbolAddress((void**)&p_t0, g_t0);
    cudaGetSymbolAddress((void**)&p_t1, g_t1);
    cudaGetSymbolAddress((void**)&p_mag, g_mag);
    cudaGetSymbolAddress((void**)&p_comb, g_comb);
    cudaGetSymbolAddress((void**)&p_h1, g_h1);
    cudaGetSymbolAddress((void**)&p_h2, g_h2);
    cudaGetSymbolAddress((void**)&p_h3, g_h3);
    cudaGetSymbolAddress((void**)&p_deep, g_deep);
    cudaGetSymbolAddress((void**)&p_ce, g_ce);
    cudaGetSymbolAddress((void**)&p_r1, g_r1);
    cudaGetSymbolAddress((void**)&p_r2, g_r2);
    cudaGetSymbolAddress((void**)&p_refined, g_refined);
    cudaGetSymbolAddress((void**)&p_q, g_q);
    cudaGetSymbolAddress((void**)&p_e, g_edge);
    cudaGetSymbolAddress((void**)&p_w, g_weak);

    const int egrid = NB / 256;
    gray_kernel<<<egrid, 256>>>(x, p_gray);

    float ks[3][5];
    gauss5(0.5f, ks[0]);
    gauss5(1.0f, ks[1]);
    gauss5(2.0f, ks[2]);
    K5 kint;
    gauss5(1.0f, kint.k);

    int dev = 0;
    cudaGetDevice(&dev);
    int sms = 0;
    cudaDeviceGetAttribute(&sms, cudaDevAttrMultiProcessorCount, dev);
    int per = 0;
    cudaOccupancyMaxActiveBlocksPerMultiprocessor(&per, hysteresis_kernel, 256, 0);
    if (per < 1) per = 1;
    int hgrid = sms * per;
    if (hgrid > NTILES) hgrid = NTILES;
    if (hgrid < 1) hgrid = 1;

    for (int s = 0; s < 3; s++) {
        K5 kv;
        for (int i = 0; i < 5; i++) kv.k[i] = ks[s][i];
        blur_v_kernel<<<egrid, 256>>>(p_gray, p_t0, kv);
        blur_h_kernel<<<egrid, 256>>>(p_t0, p_t1, kv);
        blur_v_kernel<<<egrid, 256>>>(p_t1, p_t0, kint);   // canny internal blur sigma=1
        blur_h_kernel<<<egrid, 256>>>(p_t0, p_t1, kint);
        magq_kernel<<<egrid, 256>>>(p_t1, p_mag, p_q);
        nms_kernel<<<egrid, 256>>>(p_mag, p_q, p_e, p_w);
        init_sync_kernel<<<(NTILES + 255) / 256, 256>>>();
        hysteresis_kernel<<<hgrid, dim3(32, 8)>>>(NTILES);
        combine_kernel<<<egrid, 256>>>(p_e, p_comb, s == 0 ? 1 : 0);
    }

    launch_conv<3, 16, 0>(x, wd1, bd1, p_h1);
    launch_conv<16, 16, 0>(p_h1, wd2, bd2, p_h2);
    launch_conv<16, 8, 0>(p_h2, wd3, bd3, p_h3);
    launch_conv<8, 1, 1>(p_h3, wd4, bd4, p_deep);

    pack_ce_kernel<<<egrid, 256>>>(p_comb, p_deep, p_ce);
    launch_conv<2, 8, 0>(p_ce, wr1, br1, p_r1);
    launch_conv<8, 4, 0>(p_r1, wr2, br2, p_r2);
    launch_conv<4, 1, 1>(p_r2, wr3, br3, p_refined);

    final_kernel<<<egrid, 256>>>(p_refined, p_deep, p_comb, mask, out);
}

// round 7
// speedup vs baseline: 1.0372x; 1.0372x over previous
#include <cuda_runtime.h>
#include <math.h>

constexpr int B_ = 16;
constexpr int H_ = 512;
constexpr int W_ = 512;
constexpr int NPIX = H_ * W_;
constexpr int NB = B_ * NPIX;
constexpr int NTILES = B_ * 256;

__device__ float g_gray[NB];
__device__ float g_t1[NB];
__device__ float g_mag[NB];
__device__ unsigned char g_q[NB];
__device__ unsigned char g_edge[NB];
__device__ unsigned char g_weak[NB];
__device__ float g_comb[NB];
__device__ float g_h1[16 * NB];
__device__ float g_h2[16 * NB];
__device__ float g_h3[8 * NB];
__device__ float g_deep[NB];
__device__ float g_ce[2 * NB];
__device__ float g_r1[8 * NB];
__device__ float g_r2[4 * NB];
__device__ float g_refined[NB];
__device__ int g_flags[2];
__device__ int g_barcnt;
__device__ int g_barphase;
__device__ unsigned char g_dirty[2][NTILES];

struct K5 { float k[5]; };

typedef unsigned long long ull;
__device__ __forceinline__ ull pk2(float lo, float hi) {
    ull r; asm("mov.b64 %0, {%1, %2};" : "=l"(r) : "f"(lo), "f"(hi)); return r;
}
__device__ __forceinline__ void upk2(ull v, float& lo, float& hi) {
    asm("mov.b64 {%0, %1}, %2;" : "=f"(lo), "=f"(hi) : "l"(v));
}
__device__ __forceinline__ ull fma2(ull a, ull b, ull c) {
    ull d; asm("fma.rn.f32x2 %0, %1, %2, %3;" : "=l"(d) : "l"(a), "l"(b), "l"(c)); return d;
}

// ---------------------------------------------------------------------------
// Canny decision arithmetic: FROZEN (non-FMA mul/add chains, row-major taps).
// ---------------------------------------------------------------------------
__global__ void __launch_bounds__(256) gray_kernel(const float* __restrict__ x,
                                                   float* __restrict__ gray) {
    int idx = blockIdx.x * 256 + threadIdx.x;
    if (idx >= NB) return;
    int b = idx >> 18;
    int p = idx & (NPIX - 1);
    const float* xb = x + (size_t)b * 3 * NPIX;
    float t0 = __fmul_rn(0.299f, xb[p]);
    float t1 = __fmul_rn(0.587f, xb[NPIX + p]);
    float t2 = __fmul_rn(0.114f, xb[2 * NPIX + p]);
    gray[idx] = __fadd_rn(__fadd_rn(t0, t1), t2);
}

// Fused separable 5x5 blur: vertical pass into smem, horizontal pass out.
// Identical op chains and identical bounds checks as the split kernels.
__global__ void __launch_bounds__(256) blur_fused_kernel(const float* __restrict__ in,
                                                         float* __restrict__ out, K5 kk) {
    __shared__ float s_v[16][68];
    const int tid = threadIdx.x;
    const int x0 = blockIdx.x * 64, y0 = blockIdx.y * 16;
    const int b = blockIdx.z;
    const float* ib = in + ((size_t)b << 18);
    // vertical stage: columns x0-2 .. x0+65, rows y0 .. y0+15
    for (int i = tid; i < 16 * 68; i += 256) {
        int r = i / 68, c = i % 68;
        int x = x0 + c - 2;
        if ((unsigned)x < (unsigned)W_) {
            int y = y0 + r;
            float s = 0.f;
#pragma unroll
            for (int j = 0; j < 5; j++) {
                int yy = y + j - 2;
                if ((unsigned)yy < (unsigned)H_)
                    s = __fadd_rn(s, __fmul_rn(kk.k[j], ib[yy * W_ + x]));
            }
            s_v[r][c] = s;
        }
    }
    __syncthreads();
    float* ob = out + ((size_t)b << 18);
    for (int i = tid; i < 16 * 64; i += 256) {
        int r = i / 64, c = i % 64;
        int x = x0 + c;
        float s = 0.f;
#pragma unroll
        for (int j = 0; j < 5; j++) {
            int xx = x + j - 2;
            if ((unsigned)xx < (unsigned)W_)
                s = __fadd_rn(s, __fmul_rn(kk.k[j], s_v[r][c + j]));
        }
        ob[(y0 + r) * W_ + x] = s;
    }
}

__global__ void __launch_bounds__(256) magq_kernel(const float* __restrict__ in,
                                                   float* __restrict__ mag,
                                                   unsigned char* __restrict__ q) {
    int idx = blockIdx.x * 256 + threadIdx.x;
    if (idx >= NB) return;
    int p = idx & (NPIX - 1);
    int y = p >> 9;
    int x = p & 511;
    const float* ib = in + (idx - p);
    float a[3][3];
#pragma unroll
    for (int dy = 0; dy < 3; dy++)
#pragma unroll
        for (int dx = 0; dx < 3; dx++) {
            int yy = y + dy - 1, xx = x + dx - 1;
            float v = 0.f;
            if ((unsigned)yy < (unsigned)H_ && (unsigned)xx < (unsigned)W_)
                v = ib[yy * W_ + xx];
            a[dy][dx] = v;
        }
    float gx = 0.f;
    gx = __fadd_rn(gx, __fmul_rn(-1.f, a[0][0]));
    gx = __fadd_rn(gx, __fmul_rn( 1.f, a[0][2]));
    gx = __fadd_rn(gx, __fmul_rn(-2.f, a[1][0]));
    gx = __fadd_rn(gx, __fmul_rn( 2.f, a[1][2]));
    gx = __fadd_rn(gx, __fmul_rn(-1.f, a[2][0]));
    gx = __fadd_rn(gx, __fmul_rn( 1.f, a[2][2]));
    float gy = 0.f;
    gy = __fadd_rn(gy, __fmul_rn(-1.f, a[0][0]));
    gy = __fadd_rn(gy, __fmul_rn(-2.f, a[0][1]));
    gy = __fadd_rn(gy, __fmul_rn(-1.f, a[0][2]));
    gy = __fadd_rn(gy, __fmul_rn( 1.f, a[2][0]));
    gy = __fadd_rn(gy, __fmul_rn( 2.f, a[2][1]));
    gy = __fadd_rn(gy, __fmul_rn( 1.f, a[2][2]));
    float m = sqrtf(__fadd_rn(__fadd_rn(__fmul_rn(gx, gx), __fmul_rn(gy, gy)), 1e-12f));
    // atan2f: empirically bit-identical bins vs CR atan2 on this data (R2==R3)
    float ang = atan2f(gy, gx);
    const float pi4 = 0.78539816339744830962f;
    int qi = (int)rintf(__fdiv_rn(ang, pi4));
    qi = ((qi % 4) + 4) % 4;
    mag[idx] = m;
    q[idx] = (unsigned char)qi;
}

__global__ void __launch_bounds__(256) nms_kernel(const float* __restrict__ mag,
                                                  const unsigned char* __restrict__ q,
                                                  unsigned char* __restrict__ edge,
                                                  unsigned char* __restrict__ weak) {
    int idx = blockIdx.x * 256 + threadIdx.x;
    if (idx >= NB) return;
    int p = idx & (NPIX - 1);
    int y = p >> 9;
    int x = p & 511;
    const float* mb = mag + (idx - p);
    float m = mag[idx];
    int qq = q[idx];
    int day, dax, dby, dbx;
    if (qq == 0)      { day = 0;  dax = 1;  dby = 0;  dbx = -1; }
    else if (qq == 1) { day = -1; dax = 1;  dby = 1;  dbx = -1; }
    else if (qq == 2) { day = -1; dax = 0;  dby = 1;  dbx = 0;  }
    else              { day = -1; dax = -1; dby = 1;  dbx = 1;  }
    float na = 0.f, nb = 0.f;
    {
        int yy = y + day, xx = x + dax;
        if ((unsigned)yy < (unsigned)H_ && (unsigned)xx < (unsigned)W_) na = mb[yy * W_ + xx];
        yy = y + dby; xx = x + dbx;
        if ((unsigned)yy < (unsigned)H_ && (unsigned)xx < (unsigned)W_) nb = mb[yy * W_ + xx];
    }
    float nmsv = (m >= na && m >= nb) ? m : 0.f;
    edge[idx] = (nmsv > 0.2f) ? 1 : 0;
    weak[idx] = (nmsv > 0.1f && nmsv <= 0.2f) ? 1 : 0;
}

__global__ void __launch_bounds__(256) combine_kernel(const unsigned char* __restrict__ e,
                                                      float* __restrict__ comb, int first) {
    int idx = blockIdx.x * 256 + threadIdx.x;
    if (idx >= NB) return;
    float v = (float)e[idx];
    comb[idx] = first ? v : fmaxf(comb[idx], v);
}

__global__ void __launch_bounds__(256) init_sync_kernel() {
    int i = blockIdx.x * 256 + threadIdx.x;
    if (i == 0) {
        g_flags[0] = 0;
        g_flags[1] = 0;
        g_barcnt = 0;
        g_barphase = 0;
    }
    if (i < NTILES) {
        g_dirty[0][i] = 1;
        g_dirty[1][i] = 0;
    }
}

__device__ __forceinline__ void grid_barrier(int* phase) {
    __syncthreads();
    if (threadIdx.x == 0 && threadIdx.y == 0) {
        __threadfence();
        int target = *phase + 1;
        if (atomicAdd(&g_barcnt, 1) == (int)gridDim.x - 1) {
            g_barcnt = 0;
            __threadfence();
            atomicExch(&g_barphase, target);
        } else {
            while (atomicAdd(&g_barphase, 0) < target) { __nanosleep(64); }
        }
        __threadfence();
        *phase = target;
    }
    __syncthreads();
}

__global__ void __launch_bounds__(256) hysteresis_kernel(int ntiles) {
    __shared__ unsigned char se[34][34];
    __shared__ unsigned char sw[32][32];
    const int tid = threadIdx.y * 32 + threadIdx.x;
    int phase = 0;
    for (int it = 0;; it++) {
        const int cur = it & 1, nxt = (it + 1) & 1;
        if (blockIdx.x == 0 && tid == 0) {
            ((volatile int*)g_flags)[nxt] = 0;
        }
        int any = 0;
        for (int t = blockIdx.x; t < ntiles; t += gridDim.x) {
            if (!((volatile unsigned char*)g_dirty[cur])[t]) continue;
            __syncthreads();
            if (tid == 0) g_dirty[cur][t] = 0;
            int b = t >> 8;
            int ti = t & 255;
            int ty = ti >> 4, tx = ti & 15;
            int ty0 = ty << 5, tx0 = tx << 5;
            const size_t base = (size_t)b << 18;
            for (int i = tid; i < 34 * 34; i += 256) {
                int r = i / 34, c = i % 34;
                int y = ty0 + r - 1, x = tx0 + c - 1;
                unsigned char v = 0;
                if ((unsigned)y < (unsigned)H_ && (unsigned)x < (unsigned)W_)
                    v = g_edge[base + ((size_t)y << 9) + x];
                se[r][c] = v;
            }
            bool myneed = false;
#pragma unroll
            for (int k2 = 0; k2 < 4; k2++) {
                int r = threadIdx.y + 8 * k2;
                int y = ty0 + r, x = tx0 + threadIdx.x;
                unsigned char wv = g_weak[base + ((size_t)y << 9) + x];
                sw[r][threadIdx.x] = wv;
                if (wv) myneed = true;
            }
            if (!__syncthreads_or(myneed ? 1 : 0)) continue;
            bool tilechanged = false;
            for (;;) {
                bool ch = false;
#pragma unroll
                for (int k2 = 0; k2 < 4; k2++) {
                    int r = threadIdx.y + 8 * k2;
                    int c = threadIdx.x;
                    if (sw[r][c] && !se[r + 1][c + 1]) {
                        int n = se[r][c] | se[r][c + 1] | se[r][c + 2]
                              | se[r + 1][c] | se[r + 1][c + 2]
                              | se[r + 2][c] | se[r + 2][c + 1] | se[r + 2][c + 2];
                        if (n) { se[r + 1][c + 1] = 1; ch = true; }
                    }
                }
                if (__syncthreads_or(ch ? 1 : 0)) tilechanged = true;
                else break;
            }
            if (tilechanged) {
                any = 1;
#pragma unroll
                for (int k2 = 0; k2 < 4; k2++) {
                    int r = threadIdx.y + 8 * k2;
                    int y = ty0 + r, x = tx0 + threadIdx.x;
                    g_edge[base + ((size_t)y << 9) + x] = se[r + 1][threadIdx.x + 1];
                }
                if (tid == 0) {
                    for (int dy = -1; dy <= 1; dy++)
                        for (int dx = -1; dx <= 1; dx++) {
                            if (dy == 0 && dx == 0) continue;
                            int ny = ty + dy, nx = tx + dx;
                            if ((unsigned)ny < 16u && (unsigned)nx < 16u)
                                g_dirty[nxt][(t & ~255) | (ny << 4) | nx] = 1;
                        }
                }
            }
        }
        if (any && tid == 0) ((volatile int*)g_flags)[cur] = 1;
        grid_barrier(&phase);
        int f = ((volatile int*)g_flags)[cur];
        grid_barrier(&phase);
        if (!f) break;
    }
}

// ---------------------------------------------------------------------------
// Conv v3: 32x32 tile, 256 threads, 4 px/thread, f32x2 packed accumulation,
// output channels processed in chunks of <=8 to keep registers bounded.
// ---------------------------------------------------------------------------
template <int CIN, int COUT, int ACT>
__global__ void __launch_bounds__(256) conv3x3_v3(const float* __restrict__ in,
                                                  const float* __restrict__ wt,
                                                  const float* __restrict__ bias,
                                                  float* __restrict__ out) {
    extern __shared__ float smem[];
    float* s_in = smem;                          // [CIN][34][34]
    float* s_w  = smem + CIN * 34 * 34;          // [CIN][COUT][12]
    const int tid = threadIdx.x;
    const int lx = tid & 31, ly = tid >> 5;
    const int b  = blockIdx.z;
    const int x0 = blockIdx.x * 32, y0 = blockIdx.y * 32;

    for (int i = tid; i < CIN * COUT * 12; i += 256) {
        int t  = i % 12;
        int co = (i / 12) % COUT;
        int ci = i / (12 * COUT);
        s_w[i] = (t < 9) ? wt[(co * CIN + ci) * 9 + t] : 0.f;
    }
    const float* inb = in + (size_t)b * CIN * NPIX;
    for (int i = tid; i < CIN * 34 * 34; i += 256) {
        int c  = i / (34 * 34);
        int r  = (i / 34) % 34;
        int cc = i % 34;
        int y = y0 + r - 1, x = x0 + cc - 1;
        float v = 0.f;
        if ((unsigned)y < (unsigned)H_ && (unsigned)x < (unsigned)W_)
            v = inb[(size_t)c * NPIX + y * W_ + x];
        s_in[i] = v;
    }
    __syncthreads();

    constexpr int CH = (COUT >= 8) ? 8 : COUT;
    const int ybase = ly * 4;
    float* ob = out + (size_t)b * COUT * NPIX + (y0 + ybase) * W_ + (x0 + lx);

#pragma unroll
    for (int co0 = 0; co0 < COUT; co0 += CH) {
        ull accA[CH], accB[CH];
#pragma unroll
        for (int j = 0; j < CH; j++) {
            float bv = bias[co0 + j];
            accA[j] = pk2(bv, bv);
            accB[j] = pk2(bv, bv);
        }
#pragma unroll
        for (int ci = 0; ci < CIN; ci++) {
            const float* sc = s_in + ci * (34 * 34);
            ull vA[9], vB[9];
#pragma unroll
            for (int t = 0; t < 9; t++) {
                int dy = t / 3, dx = t % 3;
                float a0 = sc[(ybase + dy) * 34 + lx + dx];
                float a1 = sc[(ybase + dy + 1) * 34 + lx + dx];
                float a2 = sc[(ybase + dy + 2) * 34 + lx + dx];
                float a3 = sc[(ybase + dy + 3) * 34 + lx + dx];
                vA[t] = pk2(a0, a1);
                vB[t] = pk2(a2, a3);
            }
#pragma unroll
            for (int j = 0; j < CH; j++) {
                const float4* wp =
                    reinterpret_cast<const float4*>(&s_w[(ci * COUT + co0 + j) * 12]);
                float4 w0 = wp[0], w1 = wp[1], w2 = wp[2];
                float w[9] = {w0.x, w0.y, w0.z, w0.w, w1.x, w1.y, w1.z, w1.w, w2.x};
#pragma unroll
                for (int t = 0; t < 9; t++) {
                    ull ww = pk2(w[t], w[t]);
                    accA[j] = fma2(vA[t], ww, accA[j]);
                    accB[j] = fma2(vB[t], ww, accB[j]);
                }
            }
        }
#pragma unroll
        for (int j = 0; j < CH; j++) {
            float p0, p1, p2, p3;
            upk2(accA[j], p0, p1);
            upk2(accB[j], p2, p3);
            float pv[4] = {p0, p1, p2, p3};
#pragma unroll
            for (int r = 0; r < 4; r++) {
                float v = pv[r];
                if (ACT == 0) v = (v >= 0.f) ? v : 0.2f * v;
                else v = 1.f / (1.f + expf(-v));
                ob[(size_t)(co0 + j) * NPIX + r * W_] = v;
            }
        }
    }
}

__global__ void __launch_bounds__(256) pack_ce_kernel(const float* __restrict__ comb,
                                                      const float* __restrict__ deep,
                                                      float* __restrict__ ce) {
    int idx = blockIdx.x * 256 + threadIdx.x;
    if (idx >= NB) return;
    int b = idx >> 18;
    int p = idx & (NPIX - 1);
    float* cb = ce + (size_t)b * 2 * NPIX;
    cb[p] = comb[idx];
    cb[NPIX + p] = deep[idx];
}

__global__ void __launch_bounds__(256) final_kernel(const float* __restrict__ refined,
                                                    const float* __restrict__ deep,
                                                    const float* __restrict__ comb,
                                                    const float* __restrict__ mask,
                                                    float* __restrict__ out) {
    int idx = blockIdx.x * 256 + threadIdx.x;
    if (idx >= NB) return;
    int b = idx >> 18;
    int p = idx & (NPIX - 1);
    float r = refined[idx];
    float d = deep[idx];
    float m = mask[idx];
    float c = comb[idx];
    float em = __fadd_rn(__fmul_rn(r, __fadd_rn(1.f, -m)),
                         __fmul_rn(__fmul_rn(d, m), 0.5f));
    const size_t T = (size_t)NB;
    out[idx] = em;
    float* ef = out + T + (size_t)b * 2 * NPIX;
    ef[p] = em;
    ef[NPIX + p] = d;
    out[3 * T + idx] = c;
    out[4 * T + idx] = d;
}

static void gauss5(float sigma, float* k) {
    float kk[5];
    for (int i = 0; i < 5; i++) {
        float r = (float)i - 2.0f;
        float rr = r * r;
        float denom = (float)(2.0 * (double)sigma * (double)sigma);
        float arg = -(rr / denom);
        kk[i] = (float)exp((double)arg);
    }
    float sum = ((((kk[0] + kk[1]) + kk[2]) + kk[3]) + kk[4]);
    for (int i = 0; i < 5; i++) k[i] = kk[i] / sum;
}

template <int CIN, int COUT, int ACT>
static void launch_conv(const float* in, const float* wt, const float* bias, float* out) {
    int smem = (CIN * 34 * 34 + CIN * COUT * 12) * (int)sizeof(float);
    if (smem > 48 * 1024) {
        cudaFuncSetAttribute(conv3x3_v3<CIN, COUT, ACT>,
                             cudaFuncAttributeMaxDynamicSharedMemorySize, smem);
    }
    dim3 grid(W_ / 32, H_ / 32, B_);
    conv3x3_v3<CIN, COUT, ACT><<<grid, 256, smem>>>(in, wt, bias, out);
}

extern "C" void kernel_launch(void* const* d_in, const int* in_sizes, int n_in,
                              void* d_out, int out_size) {
    const float* x    = (const float*)d_in[0];
    const float* mask = (const float*)d_in[1];
    const float* wd1 = (const float*)d_in[2];
    const float* bd1 = (const float*)d_in[3];
    const float* wd2 = (const float*)d_in[4];
    const float* bd2 = (const float*)d_in[5];
    const float* wd3 = (const float*)d_in[6];
    const float* bd3 = (const float*)d_in[7];
    const float* wd4 = (const float*)d_in[8];
    const float* bd4 = (const float*)d_in[9];
    const float* wr1 = (const float*)d_in[10];
    const float* br1 = (const float*)d_in[11];
    const float* wr2 = (const float*)d_in[12];
    const float* br2 = (const float*)d_in[13];
    const float* wr3 = (const float*)d_in[14];
    const float* br3 = (const float*)d_in[15];
    float* out = (float*)d_out;

    float *p_gray, *p_t0, *p_t1, *p_mag, *p_comb, *p_h1, *p_h2, *p_h3;
    float *p_deep, *p_ce, *p_r1, *p_r2, *p_refined;
    unsigned char *p_q, *p_e, *p_w;
    cudaGetSymbolAddress((void**)&p_gray, g_gray);
    cudaGetSymbolAddress((void**)&p_t1, g_t1);
    p_t0 = p_t1;  // fused blur no longer needs a second temp; alias
    cudaGetSymbolAddress((void**)&p_mag, g_mag);
    cudaGetSymbolAddress((void**)&p_comb, g_comb);
    cudaGetSymbolAddress((void**)&p_h1, g_h1);
    cudaGetSymbolAddress((void**)&p_h2, g_h2);
    cudaGetSymbolAddress((void**)&p_h3, g_h3);
    cudaGetSymbolAddress((void**)&p_deep, g_deep);
    cudaGetSymbolAddress((void**)&p_ce, g_ce);
    cudaGetSymbolAddress((void**)&p_r1, g_r1);
    cudaGetSymbolAddress((void**)&p_r2, g_r2);
    cudaGetSymbolAddress((void**)&p_refined, g_refined);
    cudaGetSymbolAddress((void**)&p_q, g_q);
    cudaGetSymbolAddress((void**)&p_e, g_edge);
    cudaGetSymbolAddress((void**)&p_w, g_weak);
    float* p_tmp;
    cudaGetSymbolAddress((void**)&p_tmp, g_h1);  // reuse conv scratch as blur temp

    const int egrid = NB / 256;
    gray_kernel<<<egrid, 256>>>(x, p_gray);

    float ks[3][5];
    gauss5(0.5f, ks[0]);
    gauss5(1.0f, ks[1]);
    gauss5(2.0f, ks[2]);
    K5 kint;
    gauss5(1.0f, kint.k);

    int dev = 0;
    cudaGetDevice(&dev);
    int sms = 0;
    cudaDeviceGetAttribute(&sms, cudaDevAttrMultiProcessorCount, dev);
    int per = 0;
    cudaOccupancyMaxActiveBlocksPerMultiprocessor(&per, hysteresis_kernel, 256, 0);
    if (per < 1) per = 1;
    int hgrid = sms * per;
    if (hgrid > NTILES) hgrid = NTILES;
    if (hgrid < 1) hgrid = 1;

    dim3 bgrid(W_ / 64, H_ / 16, B_);
    for (int s = 0; s < 3; s++) {
        K5 kv;
        for (int i = 0; i < 5; i++) kv.k[i] = ks[s][i];
        blur_fused_kernel<<<bgrid, 256>>>(p_gray, p_tmp, kv);
        blur_fused_kernel<<<bgrid, 256>>>(p_tmp, p_t1, kint);  // canny internal sigma=1
        magq_kernel<<<egrid, 256>>>(p_t1, p_mag, p_q);
        nms_kernel<<<egrid, 256>>>(p_mag, p_q, p_e, p_w);
        init_sync_kernel<<<(NTILES + 255) / 256, 256>>>();
        hysteresis_kernel<<<hgrid, dim3(32, 8)>>>(NTILES);
        combine_kernel<<<egrid, 256>>>(p_e, p_comb, s == 0 ? 1 : 0);
    }

    launch_conv<3, 16, 0>(x, wd1, bd1, p_h1);
    launch_conv<16, 16, 0>(p_h1, wd2, bd2, p_h2);
    launch_conv<16, 8, 0>(p_h2, wd3, bd3, p_h3);
    launch_conv<8, 1, 1>(p_h3, wd4, bd4, p_deep);

    pack_ce_kernel<<<egrid, 256>>>(p_comb, p_deep, p_ce);
    launch_conv<2, 8, 0>(p_ce, wr1, br1, p_r1);
    launch_conv<8, 4, 0>(p_r1, wr2, br2, p_r2);
    launch_conv<4, 1, 1>(p_r2, wr3, br3, p_refined);

    final_kernel<<<egrid, 256>>>(p_refined, p_deep, p_comb, mask, out);
}

// round 9
// speedup vs baseline: 1.0559x; 1.0180x over previous
#include <cuda_runtime.h>
#include <math.h>

constexpr int B_ = 16;
constexpr int H_ = 512;
constexpr int W_ = 512;
constexpr int NPIX = H_ * W_;
constexpr int NB = B_ * NPIX;          // 4,194,304
constexpr int NS = 3;                  // sigmas
constexpr int NIMG = NS * B_;          // 48 batched images
constexpr int NB3 = NS * NB;
constexpr int NTILES3 = NIMG * 256;    // 12288 tiles (32x32)

__device__ float g_gray[NB];
__device__ float g_t1[NB3];
__device__ float g_mag[NB3];
__device__ unsigned char g_q[NB3];
__device__ unsigned char g_edge[NB3];
__device__ unsigned char g_weak[NB3];
__device__ float g_comb[NB];
__device__ float g_h1[16 * NB];
__device__ float g_h2[16 * NB];
__device__ float g_h3[8 * NB];
__device__ float g_deep[NB];
__device__ float g_ce[2 * NB];
__device__ float g_r1[8 * NB];
__device__ float g_r2[4 * NB];
__device__ float g_refined[NB];
__device__ int g_flags[2];
__device__ int g_barcnt;
__device__ int g_barphase;
__device__ unsigned char g_dirty[2][NTILES3];

struct K5 { float k[5]; };
struct K53 { float k[3][5]; };

typedef unsigned long long ull;
__device__ __forceinline__ ull pk2(float lo, float hi) {
    ull r; asm("mov.b64 %0, {%1, %2};" : "=l"(r) : "f"(lo), "f"(hi)); return r;
}
__device__ __forceinline__ void upk2(ull v, float& lo, float& hi) {
    asm("mov.b64 {%0, %1}, %2;" : "=f"(lo), "=f"(hi) : "l"(v));
}
__device__ __forceinline__ ull fma2(ull a, ull b, ull c) {
    ull d; asm("fma.rn.f32x2 %0, %1, %2, %3;" : "=l"(d) : "l"(a), "l"(b), "l"(c)); return d;
}

// ---------------------------------------------------------------------------
// Canny decision arithmetic: FROZEN (non-FMA mul/add chains, row-major taps).
// ---------------------------------------------------------------------------
__global__ void __launch_bounds__(256) gray_kernel(const float* __restrict__ x,
                                                   float* __restrict__ gray) {
    int idx = blockIdx.x * 256 + threadIdx.x;
    if (idx >= NB) return;
    int b = idx >> 18;
    int p = idx & (NPIX - 1);
    const float* xb = x + (size_t)b * 3 * NPIX;
    float t0 = __fmul_rn(0.299f, xb[p]);
    float t1 = __fmul_rn(0.587f, xb[NPIX + p]);
    float t2 = __fmul_rn(0.114f, xb[2 * NPIX + p]);
    gray[idx] = __fadd_rn(__fadd_rn(t0, t1), t2);
}

// Batched fused separable 5x5 blur #1: gray (NB) -> tmp (NB3), sigma-specific taps
__global__ void __launch_bounds__(256) blur1_batched(const float* __restrict__ in,
                                                     float* __restrict__ out, K53 kks) {
    __shared__ float s_v[16][68];
    const int tid = threadIdx.x;
    const int x0 = blockIdx.x * 64, y0 = blockIdx.y * 16;
    const int img = blockIdx.z;                // 0..47
    const int sg = img >> 4;                   // sigma index
    const int b = img & 15;
    const float* kk = kks.k[sg];
    const float* ib = in + ((size_t)b << 18);
    for (int i = tid; i < 16 * 68; i += 256) {
        int r = i / 68, c = i % 68;
        int x = x0 + c - 2;
        if ((unsigned)x < (unsigned)W_) {
            int y = y0 + r;
            float s = 0.f;
#pragma unroll
            for (int j = 0; j < 5; j++) {
                int yy = y + j - 2;
                if ((unsigned)yy < (unsigned)H_)
                    s = __fadd_rn(s, __fmul_rn(kk[j], ib[yy * W_ + x]));
            }
            s_v[r][c] = s;
        }
    }
    __syncthreads();
    float* ob = out + ((size_t)img << 18);
    for (int i = tid; i < 16 * 64; i += 256) {
        int r = i / 64, c = i % 64;
        int x = x0 + c;
        float s = 0.f;
#pragma unroll
        for (int j = 0; j < 5; j++) {
            int xx = x + j - 2;
            if ((unsigned)xx < (unsigned)W_)
                s = __fadd_rn(s, __fmul_rn(kk[j], s_v[r][c + j]));
        }
        ob[(y0 + r) * W_ + x] = s;
    }
}

// Batched fused blur #2 (canny internal sigma=1): tmp (NB3) -> t1 (NB3)
__global__ void __launch_bounds__(256) blur2_batched(const float* __restrict__ in,
                                                     float* __restrict__ out, K5 kk) {
    __shared__ float s_v[16][68];
    const int tid = threadIdx.x;
    const int x0 = blockIdx.x * 64, y0 = blockIdx.y * 16;
    const int img = blockIdx.z;
    const float* ib = in + ((size_t)img << 18);
    for (int i = tid; i < 16 * 68; i += 256) {
        int r = i / 68, c = i % 68;
        int x = x0 + c - 2;
        if ((unsigned)x < (unsigned)W_) {
            int y = y0 + r;
            float s = 0.f;
#pragma unroll
            for (int j = 0; j < 5; j++) {
                int yy = y + j - 2;
                if ((unsigned)yy < (unsigned)H_)
                    s = __fadd_rn(s, __fmul_rn(kk.k[j], ib[yy * W_ + x]));
            }
            s_v[r][c] = s;
        }
    }
    __syncthreads();
    float* ob = out + ((size_t)img << 18);
    for (int i = tid; i < 16 * 64; i += 256) {
        int r = i / 64, c = i % 64;
        int x = x0 + c;
        float s = 0.f;
#pragma unroll
        for (int j = 0; j < 5; j++) {
            int xx = x + j - 2;
            if ((unsigned)xx < (unsigned)W_)
                s = __fadd_rn(s, __fmul_rn(kk.k[j], s_v[r][c + j]));
        }
        ob[(y0 + r) * W_ + x] = s;
    }
}

__global__ void __launch_bounds__(256) magq_kernel(const float* __restrict__ in,
                                                   float* __restrict__ mag,
                                                   unsigned char* __restrict__ q) {
    int idx = blockIdx.x * 256 + threadIdx.x;
    if (idx >= NB3) return;
    int p = idx & (NPIX - 1);
    int y = p >> 9;
    int x = p & 511;
    const float* ib = in + (idx - p);
    float a[3][3];
#pragma unroll
    for (int dy = 0; dy < 3; dy++)
#pragma unroll
        for (int dx = 0; dx < 3; dx++) {
            int yy = y + dy - 1, xx = x + dx - 1;
            float v = 0.f;
            if ((unsigned)yy < (unsigned)H_ && (unsigned)xx < (unsigned)W_)
                v = ib[yy * W_ + xx];
            a[dy][dx] = v;
        }
    float gx = 0.f;
    gx = __fadd_rn(gx, __fmul_rn(-1.f, a[0][0]));
    gx = __fadd_rn(gx, __fmul_rn( 1.f, a[0][2]));
    gx = __fadd_rn(gx, __fmul_rn(-2.f, a[1][0]));
    gx = __fadd_rn(gx, __fmul_rn( 2.f, a[1][2]));
    gx = __fadd_rn(gx, __fmul_rn(-1.f, a[2][0]));
    gx = __fadd_rn(gx, __fmul_rn( 1.f, a[2][2]));
    float gy = 0.f;
    gy = __fadd_rn(gy, __fmul_rn(-1.f, a[0][0]));
    gy = __fadd_rn(gy, __fmul_rn(-2.f, a[0][1]));
    gy = __fadd_rn(gy, __fmul_rn(-1.f, a[0][2]));
    gy = __fadd_rn(gy, __fmul_rn( 1.f, a[2][0]));
    gy = __fadd_rn(gy, __fmul_rn( 2.f, a[2][1]));
    gy = __fadd_rn(gy, __fmul_rn( 1.f, a[2][2]));
    float m = sqrtf(__fadd_rn(__fadd_rn(__fmul_rn(gx, gx), __fmul_rn(gy, gy)), 1e-12f));
    float ang = atan2f(gy, gx);
    const float pi4 = 0.78539816339744830962f;
    int qi = (int)rintf(__fdiv_rn(ang, pi4));
    qi = ((qi % 4) + 4) % 4;
    mag[idx] = m;
    q[idx] = (unsigned char)qi;
}

__global__ void __launch_bounds__(256) nms_kernel(const float* __restrict__ mag,
                                                  const unsigned char* __restrict__ q,
                                                  unsigned char* __restrict__ edge,
                                                  unsigned char* __restrict__ weak) {
    int idx = blockIdx.x * 256 + threadIdx.x;
    if (idx >= NB3) return;
    int p = idx & (NPIX - 1);
    int y = p >> 9;
    int x = p & 511;
    const float* mb = mag + (idx - p);
    float m = mag[idx];
    int qq = q[idx];
    int day, dax, dby, dbx;
    if (qq == 0)      { day = 0;  dax = 1;  dby = 0;  dbx = -1; }
    else if (qq == 1) { day = -1; dax = 1;  dby = 1;  dbx = -1; }
    else if (qq == 2) { day = -1; dax = 0;  dby = 1;  dbx = 0;  }
    else              { day = -1; dax = -1; dby = 1;  dbx = 1;  }
    float na = 0.f, nb = 0.f;
    {
        int yy = y + day, xx = x + dax;
        if ((unsigned)yy < (unsigned)H_ && (unsigned)xx < (unsigned)W_) na = mb[yy * W_ + xx];
        yy = y + dby; xx = x + dbx;
        if ((unsigned)yy < (unsigned)H_ && (unsigned)xx < (unsigned)W_) nb = mb[yy * W_ + xx];
    }
    float nmsv = (m >= na && m >= nb) ? m : 0.f;
    edge[idx] = (nmsv > 0.2f) ? 1 : 0;
    weak[idx] = (nmsv > 0.1f && nmsv <= 0.2f) ? 1 : 0;
}

// combined_canny = max over sigmas of final edges
__global__ void __launch_bounds__(256) combine3_kernel(const unsigned char* __restrict__ e,
                                                       float* __restrict__ comb) {
    int idx = blockIdx.x * 256 + threadIdx.x;
    if (idx >= NB) return;
    unsigned char v = e[idx] | e[NB + idx] | e[2 * NB + idx];
    comb[idx] = (float)v;
}

__global__ void __launch_bounds__(256) init_sync_kernel() {
    int i = blockIdx.x * 256 + threadIdx.x;
    if (i == 0) {
        g_flags[0] = 0;
        g_flags[1] = 0;
        g_barcnt = 0;
        g_barphase = 0;
    }
    if (i < NTILES3) {
        g_dirty[0][i] = 1;
        g_dirty[1][i] = 0;
    }
}

__device__ __forceinline__ void grid_barrier(int* phase) {
    __syncthreads();
    if (threadIdx.x == 0 && threadIdx.y == 0) {
        __threadfence();
        int target = *phase + 1;
        if (atomicAdd(&g_barcnt, 1) == (int)gridDim.x - 1) {
            g_barcnt = 0;
            __threadfence();
            atomicExch(&g_barphase, target);
        } else {
            while (atomicAdd(&g_barphase, 0) < target) { __nanosleep(64); }
        }
        __threadfence();
        *phase = target;
    }
    __syncthreads();
}

// One persistent launch covers all 48 images (3 sigmas x 16 batch).
__global__ void __launch_bounds__(256) hysteresis_kernel(int ntiles) {
    __shared__ unsigned char se[34][34];
    __shared__ unsigned char sw[32][32];
    const int tid = threadIdx.y * 32 + threadIdx.x;
    int phase = 0;
    for (int it = 0;; it++) {
        const int cur = it & 1, nxt = (it + 1) & 1;
        if (blockIdx.x == 0 && tid == 0) {
            ((volatile int*)g_flags)[nxt] = 0;
        }
        int any = 0;
        for (int t = blockIdx.x; t < ntiles; t += gridDim.x) {
            if (!((volatile unsigned char*)g_dirty[cur])[t]) continue;
            __syncthreads();
            if (tid == 0) g_dirty[cur][t] = 0;
            int img = t >> 8;
            int ti = t & 255;
            int ty = ti >> 4, tx = ti & 15;
            int ty0 = ty << 5, tx0 = tx << 5;
            const size_t base = (size_t)img << 18;
            for (int i = tid; i < 34 * 34; i += 256) {
                int r = i / 34, c = i % 34;
                int y = ty0 + r - 1, x = tx0 + c - 1;
                unsigned char v = 0;
                if ((unsigned)y < (unsigned)H_ && (unsigned)x < (unsigned)W_)
                    v = g_edge[base + ((size_t)y << 9) + x];
                se[r][c] = v;
            }
            bool myneed = false;
#pragma unroll
            for (int k2 = 0; k2 < 4; k2++) {
                int r = threadIdx.y + 8 * k2;
                int y = ty0 + r, x = tx0 + threadIdx.x;
                unsigned char wv = g_weak[base + ((size_t)y << 9) + x];
                sw[r][threadIdx.x] = wv;
                if (wv) myneed = true;
            }
            if (!__syncthreads_or(myneed ? 1 : 0)) continue;
            bool tilechanged = false;
            for (;;) {
                bool ch = false;
#pragma unroll
                for (int k2 = 0; k2 < 4; k2++) {
                    int r = threadIdx.y + 8 * k2;
                    int c = threadIdx.x;
                    if (sw[r][c] && !se[r + 1][c + 1]) {
                        int n = se[r][c] | se[r][c + 1] | se[r][c + 2]
                              | se[r + 1][c] | se[r + 1][c + 2]
                              | se[r + 2][c] | se[r + 2][c + 1] | se[r + 2][c + 2];
                        if (n) { se[r + 1][c + 1] = 1; ch = true; }
                    }
                }
                if (__syncthreads_or(ch ? 1 : 0)) tilechanged = true;
                else break;
            }
            if (tilechanged) {
                any = 1;
#pragma unroll
                for (int k2 = 0; k2 < 4; k2++) {
                    int r = threadIdx.y + 8 * k2;
                    int y = ty0 + r, x = tx0 + threadIdx.x;
                    g_edge[base + ((size_t)y << 9) + x] = se[r + 1][threadIdx.x + 1];
                }
                if (tid == 0) {
                    for (int dy = -1; dy <= 1; dy++)
                        for (int dx = -1; dx <= 1; dx++) {
                            if (dy == 0 && dx == 0) continue;
                            int ny = ty + dy, nx = tx + dx;
                            if ((unsigned)ny < 16u && (unsigned)nx < 16u)
                                g_dirty[nxt][(t & ~255) | (ny << 4) | nx] = 1;
                        }
                }
            }
        }
        if (any && tid == 0) ((volatile int*)g_flags)[cur] = 1;
        grid_barrier(&phase);
        int f = ((volatile int*)g_flags)[cur];
        grid_barrier(&phase);
        if (!f) break;
    }
}

// ---------------------------------------------------------------------------
// Conv v3 (unchanged from round 7)
// ---------------------------------------------------------------------------
template <int CIN, int COUT, int ACT>
__global__ void __launch_bounds__(256) conv3x3_v3(const float* __restrict__ in,
                                                  const float* __restrict__ wt,
                                                  const float* __restrict__ bias,
                                                  float* __restrict__ out) {
    extern __shared__ float smem[];
    float* s_in = smem;
    float* s_w  = smem + CIN * 34 * 34;
    const int tid = threadIdx.x;
    const int lx = tid & 31, ly = tid >> 5;
    const int b  = blockIdx.z;
    const int x0 = blockIdx.x * 32, y0 = blockIdx.y * 32;

    for (int i = tid; i < CIN * COUT * 12; i += 256) {
        int t  = i % 12;
        int co = (i / 12) % COUT;
        int ci = i / (12 * COUT);
        s_w[i] = (t < 9) ? wt[(co * CIN + ci) * 9 + t] : 0.f;
    }
    const float* inb = in + (size_t)b * CIN * NPIX;
    for (int i = tid; i < CIN * 34 * 34; i += 256) {
        int c  = i / (34 * 34);
        int r  = (i / 34) % 34;
        int cc = i % 34;
        int y = y0 + r - 1, x = x0 + cc - 1;
        float v = 0.f;
        if ((unsigned)y < (unsigned)H_ && (unsigned)x < (unsigned)W_)
            v = inb[(size_t)c * NPIX + y * W_ + x];
        s_in[i] = v;
    }
    __syncthreads();

    constexpr int CH = (COUT >= 8) ? 8 : COUT;
    const int ybase = ly * 4;
    float* ob = out + (size_t)b * COUT * NPIX + (y0 + ybase) * W_ + (x0 + lx);

#pragma unroll
    for (int co0 = 0; co0 < COUT; co0 += CH) {
        ull accA[CH], accB[CH];
#pragma unroll
        for (int j = 0; j < CH; j++) {
            float bv = bias[co0 + j];
            accA[j] = pk2(bv, bv);
            accB[j] = pk2(bv, bv);
        }
#pragma unroll
        for (int ci = 0; ci < CIN; ci++) {
            const float* sc = s_in + ci * (34 * 34);
            ull vA[9], vB[9];
#pragma unroll
            for (int t = 0; t < 9; t++) {
                int dy = t / 3, dx = t % 3;
                float a0 = sc[(ybase + dy) * 34 + lx + dx];
                float a1 = sc[(ybase + dy + 1) * 34 + lx + dx];
                float a2 = sc[(ybase + dy + 2) * 34 + lx + dx];
                float a3 = sc[(ybase + dy + 3) * 34 + lx + dx];
                vA[t] = pk2(a0, a1);
                vB[t] = pk2(a2, a3);
            }
#pragma unroll
            for (int j = 0; j < CH; j++) {
                const float4* wp =
                    reinterpret_cast<const float4*>(&s_w[(ci * COUT + co0 + j) * 12]);
                float4 w0 = wp[0], w1 = wp[1], w2 = wp[2];
                float w[9] = {w0.x, w0.y, w0.z, w0.w, w1.x, w1.y, w1.z, w1.w, w2.x};
#pragma unroll
                for (int t = 0; t < 9; t++) {
                    ull ww = pk2(w[t], w[t]);
                    accA[j] = fma2(vA[t], ww, accA[j]);
                    accB[j] = fma2(vB[t], ww, accB[j]);
                }
            }
        }
#pragma unroll
        for (int j = 0; j < CH; j++) {
            float p0, p1, p2, p3;
            upk2(accA[j], p0, p1);
            upk2(accB[j], p2, p3);
            float pv[4] = {p0, p1, p2, p3};
#pragma unroll
            for (int r = 0; r < 4; r++) {
                float v = pv[r];
                if (ACT == 0) v = (v >= 0.f) ? v : 0.2f * v;
                else v = 1.f / (1.f + expf(-v));
                ob[(size_t)(co0 + j) * NPIX + r * W_] = v;
            }
        }
    }
}

__global__ void __launch_bounds__(256) pack_ce_kernel(const float* __restrict__ comb,
                                                      const float* __restrict__ deep,
                                                      float* __restrict__ ce) {
    int idx = blockIdx.x * 256 + threadIdx.x;
    if (idx >= NB) return;
    int b = idx >> 18;
    int p = idx & (NPIX - 1);
    float* cb = ce + (size_t)b * 2 * NPIX;
    cb[p] = comb[idx];
    cb[NPIX + p] = deep[idx];
}

__global__ void __launch_bounds__(256) final_kernel(const float* __restrict__ refined,
                                                    const float* __restrict__ deep,
                                                    const float* __restrict__ comb,
                                                    const float* __restrict__ mask,
                                                    float* __restrict__ out) {
    int idx = blockIdx.x * 256 + threadIdx.x;
    if (idx >= NB) return;
    int b = idx >> 18;
    int p = idx & (NPIX - 1);
    float r = refined[idx];
    float d = deep[idx];
    float m = mask[idx];
    float c = comb[idx];
    float em = __fadd_rn(__fmul_rn(r, __fadd_rn(1.f, -m)),
                         __fmul_rn(__fmul_rn(d, m), 0.5f));
    const size_t T = (size_t)NB;
    out[idx] = em;
    float* ef = out + T + (size_t)b * 2 * NPIX;
    ef[p] = em;
    ef[NPIX + p] = d;
    out[3 * T + idx] = c;
    out[4 * T + idx] = d;
}

static void gauss5(float sigma, float* k) {
    float kk[5];
    for (int i = 0; i < 5; i++) {
        float r = (float)i - 2.0f;
        float rr = r * r;
        float denom = (float)(2.0 * (double)sigma * (double)sigma);
        float arg = -(rr / denom);
        kk[i] = (float)exp((double)arg);
    }
    float sum = ((((kk[0] + kk[1]) + kk[2]) + kk[3]) + kk[4]);
    for (int i = 0; i < 5; i++) k[i] = kk[i] / sum;
}

template <int CIN, int COUT, int ACT>
static void launch_conv(const float* in, const float* wt, const float* bias, float* out) {
    int smem = (CIN * 34 * 34 + CIN * COUT * 12) * (int)sizeof(float);
    if (smem > 48 * 1024) {
        cudaFuncSetAttribute(conv3x3_v3<CIN, COUT, ACT>,
                             cudaFuncAttributeMaxDynamicSharedMemorySize, smem);
    }
    dim3 grid(W_ / 32, H_ / 32, B_);
    conv3x3_v3<CIN, COUT, ACT><<<grid, 256, smem>>>(in, wt, bias, out);
}

extern "C" void kernel_launch(void* const* d_in, const int* in_sizes, int n_in,
                              void* d_out, int out_size) {
    const float* x    = (const float*)d_in[0];
    const float* mask = (const float*)d_in[1];
    const float* wd1 = (const float*)d_in[2];
    const float* bd1 = (const float*)d_in[3];
    const float* wd2 = (const float*)d_in[4];
    const float* bd2 = (const float*)d_in[5];
    const float* wd3 = (const float*)d_in[6];
    const float* bd3 = (const float*)d_in[7];
    const float* wd4 = (const float*)d_in[8];
    const float* bd4 = (const float*)d_in[9];
    const float* wr1 = (const float*)d_in[10];
    const float* br1 = (const float*)d_in[11];
    const float* wr2 = (const float*)d_in[12];
    const float* br2 = (const float*)d_in[13];
    const float* wr3 = (const float*)d_in[14];
    const float* br3 = (const float*)d_in[15];
    float* out = (float*)d_out;

    float *p_gray, *p_t1, *p_mag, *p_comb, *p_h1, *p_h2, *p_h3;
    float *p_deep, *p_ce, *p_r1, *p_r2, *p_refined, *p_tmp;
    unsigned char *p_q, *p_e, *p_w;
    cudaGetSymbolAddress((void**)&p_gray, g_gray);
    cudaGetSymbolAddress((void**)&p_t1, g_t1);
    cudaGetSymbolAddress((void**)&p_mag, g_mag);
    cudaGetSymbolAddress((void**)&p_comb, g_comb);
    cudaGetSymbolAddress((void**)&p_h1, g_h1);
    cudaGetSymbolAddress((void**)&p_h2, g_h2);
    cudaGetSymbolAddress((void**)&p_h3, g_h3);
    cudaGetSymbolAddress((void**)&p_deep, g_deep);
    cudaGetSymbolAddress((void**)&p_ce, g_ce);
    cudaGetSymbolAddress((void**)&p_r1, g_r1);
    cudaGetSymbolAddress((void**)&p_r2, g_r2);
    cudaGetSymbolAddress((void**)&p_refined, g_refined);
    cudaGetSymbolAddress((void**)&p_q, g_q);
    cudaGetSymbolAddress((void**)&p_e, g_edge);
    cudaGetSymbolAddress((void**)&p_w, g_weak);
    cudaGetSymbolAddress((void**)&p_tmp, g_h1);   // reuse conv scratch (16NB >= 3NB)

    const int egrid = NB / 256;
    const int egrid3 = NB3 / 256;
    gray_kernel<<<egrid, 256>>>(x, p_gray);

    K53 kall;
    gauss5(0.5f, kall.k[0]);
    gauss5(1.0f, kall.k[1]);
    gauss5(2.0f, kall.k[2]);
    K5 kint;
    gauss5(1.0f, kint.k);

    int dev = 0;
    cudaGetDevice(&dev);
    int sms = 0;
    cudaDeviceGetAttribute(&sms, cudaDevAttrMultiProcessorCount, dev);
    int per = 0;
    cudaOccupancyMaxActiveBlocksPerMultiprocessor(&per, hysteresis_kernel, 256, 0);
    if (per < 1) per = 1;
    if (per > 2) per = 2;                 // cap: barrier cost scales with block count
    int hgrid = sms * per;
    if (hgrid > NTILES3) hgrid = NTILES3;
    if (hgrid < 1) hgrid = 1;

    // Batched canny across all 3 sigmas x 16 images
    dim3 bgrid(W_ / 64, H_ / 16, NIMG);
    blur1_batched<<<bgrid, 256>>>(p_gray, p_tmp, kall);
    blur2_batched<<<bgrid, 256>>>(p_tmp, p_t1, kint);
    magq_kernel<<<egrid3, 256>>>(p_t1, p_mag, p_q);
    nms_kernel<<<egrid3, 256>>>(p_mag, p_q, p_e, p_w);
    init_sync_kernel<<<(NTILES3 + 255) / 256, 256>>>();
    hysteresis_kernel<<<hgrid, dim3(32, 8)>>>(NTILES3);
    combine3_kernel<<<egrid, 256>>>(p_e, p_comb);

    launch_conv<3, 16, 0>(x, wd1, bd1, p_h1);
    launch_conv<16, 16, 0>(p_h1, wd2, bd2, p_h2);
    launch_conv<16, 8, 0>(p_h2, wd3, bd3, p_h3);
    launch_conv<8, 1, 1>(p_h3, wd4, bd4, p_deep);

    pack_ce_kernel<<<egrid, 256>>>(p_comb, p_deep, p_ce);
    launch_conv<2, 8, 0>(p_ce, wr1, br1, p_r1);
    launch_conv<8, 4, 0>(p_r1, wr2, br2, p_r2);
    launch_conv<4, 1, 1>(p_r2, wr3, br3, p_refined);

    final_kernel<<<egrid, 256>>>(p_refined, p_deep, p_comb, mask, out);
}

// round 12
// speedup vs baseline: 1.2577x; 1.1912x over previous
#include <cuda_runtime.h>
#include <math.h>

constexpr int B_ = 16;
constexpr int H_ = 512;
constexpr int W_ = 512;
constexpr int NPIX = H_ * W_;
constexpr int NB = B_ * NPIX;          // 4,194,304
constexpr int NS = 3;
constexpr int NIMG = NS * B_;          // 48
constexpr int NB3 = NS * NB;
constexpr int NTILES = NIMG * 64;      // 3072 tiles of 64x64
constexpr int NWORDS = NB3 / 32;       // bitmap words (uint32)

__device__ float g_gray[NB];
__device__ float g_t1[NB3];
__device__ float g_mag[NB3];
__device__ unsigned char g_q[NB3];
__device__ unsigned g_ebits[NWORDS];
__device__ unsigned g_wbits[NWORDS];
__device__ float g_comb[NB];
__device__ float g_h1[16 * NB];
__device__ float g_h2[16 * NB];
__device__ float g_h3[8 * NB];
__device__ float g_deep[NB];
__device__ float g_ce[2 * NB];
__device__ float g_r1[8 * NB];
__device__ float g_r2[4 * NB];
__device__ float g_refined[NB];
__device__ int g_swflags[4];
__device__ int g_barcnt;
__device__ int g_barphase;
__device__ unsigned char g_dirty[2][NTILES];

struct K5 { float k[5]; };
struct K53 { float k[3][5]; };

typedef unsigned long long ull;
__device__ __forceinline__ ull pk2(float lo, float hi) {
    ull r; asm("mov.b64 %0, {%1, %2};" : "=l"(r) : "f"(lo), "f"(hi)); return r;
}
__device__ __forceinline__ void upk2(ull v, float& lo, float& hi) {
    asm("mov.b64 {%0, %1}, %2;" : "=f"(lo), "=f"(hi) : "l"(v));
}
__device__ __forceinline__ ull fma2(ull a, ull b, ull c) {
    ull d; asm("fma.rn.f32x2 %0, %1, %2, %3;" : "=l"(d) : "l"(a), "l"(b), "l"(c)); return d;
}

// ---------------------------------------------------------------------------
// Canny decision arithmetic: FROZEN (non-FMA mul/add chains, row-major taps).
// ---------------------------------------------------------------------------
__global__ void __launch_bounds__(256) gray_kernel(const float* __restrict__ x,
                                                   float* __restrict__ gray) {
    int idx = blockIdx.x * 256 + threadIdx.x;
    if (idx >= NB) return;
    int b = idx >> 18;
    int p = idx & (NPIX - 1);
    const float* xb = x + (size_t)b * 3 * NPIX;
    float t0 = __fmul_rn(0.299f, xb[p]);
    float t1 = __fmul_rn(0.587f, xb[NPIX + p]);
    float t2 = __fmul_rn(0.114f, xb[2 * NPIX + p]);
    gray[idx] = __fadd_rn(__fadd_rn(t0, t1), t2);
}

__global__ void __launch_bounds__(256) blur1_batched(const float* __restrict__ in,
                                                     float* __restrict__ out, K53 kks) {
    __shared__ float s_v[16][68];
    const int tid = threadIdx.x;
    const int x0 = blockIdx.x * 64, y0 = blockIdx.y * 16;
    const int img = blockIdx.z;
    const int sg = img >> 4;
    const int b = img & 15;
    const float* kk = kks.k[sg];
    const float* ib = in + ((size_t)b << 18);
    for (int i = tid; i < 16 * 68; i += 256) {
        int r = i / 68, c = i % 68;
        int x = x0 + c - 2;
        if ((unsigned)x < (unsigned)W_) {
            int y = y0 + r;
            float s = 0.f;
#pragma unroll
            for (int j = 0; j < 5; j++) {
                int yy = y + j - 2;
                if ((unsigned)yy < (unsigned)H_)
                    s = __fadd_rn(s, __fmul_rn(kk[j], ib[yy * W_ + x]));
            }
            s_v[r][c] = s;
        }
    }
    __syncthreads();
    float* ob = out + ((size_t)img << 18);
    for (int i = tid; i < 16 * 64; i += 256) {
        int r = i / 64, c = i % 64;
        int x = x0 + c;
        float s = 0.f;
#pragma unroll
        for (int j = 0; j < 5; j++) {
            int xx = x + j - 2;
            if ((unsigned)xx < (unsigned)W_)
                s = __fadd_rn(s, __fmul_rn(kk[j], s_v[r][c + j]));
        }
        ob[(y0 + r) * W_ + x] = s;
    }
}

__global__ void __launch_bounds__(256) blur2_batched(const float* __restrict__ in,
                                                     float* __restrict__ out, K5 kk) {
    __shared__ float s_v[16][68];
    const int tid = threadIdx.x;
    const int x0 = blockIdx.x * 64, y0 = blockIdx.y * 16;
    const int img = blockIdx.z;
    const float* ib = in + ((size_t)img << 18);
    for (int i = tid; i < 16 * 68; i += 256) {
        int r = i / 68, c = i % 68;
        int x = x0 + c - 2;
        if ((unsigned)x < (unsigned)W_) {
            int y = y0 + r;
            float s = 0.f;
#pragma unroll
            for (int j = 0; j < 5; j++) {
                int yy = y + j - 2;
                if ((unsigned)yy < (unsigned)H_)
                    s = __fadd_rn(s, __fmul_rn(kk.k[j], ib[yy * W_ + x]));
            }
            s_v[r][c] = s;
        }
    }
    __syncthreads();
    float* ob = out + ((size_t)img << 18);
    for (int i = tid; i < 16 * 64; i += 256) {
        int r = i / 64, c = i % 64;
        int x = x0 + c;
        float s = 0.f;
#pragma unroll
        for (int j = 0; j < 5; j++) {
            int xx = x + j - 2;
            if ((unsigned)xx < (unsigned)W_)
                s = __fadd_rn(s, __fmul_rn(kk.k[j], s_v[r][c + j]));
        }
        ob[(y0 + r) * W_ + x] = s;
    }
}

__global__ void __launch_bounds__(256) magq_kernel(const float* __restrict__ in,
                                                   float* __restrict__ mag,
                                                   unsigned char* __restrict__ q) {
    int idx = blockIdx.x * 256 + threadIdx.x;
    if (idx >= NB3) return;
    int p = idx & (NPIX - 1);
    int y = p >> 9;
    int x = p & 511;
    const float* ib = in + (idx - p);
    float a[3][3];
#pragma unroll
    for (int dy = 0; dy < 3; dy++)
#pragma unroll
        for (int dx = 0; dx < 3; dx++) {
            int yy = y + dy - 1, xx = x + dx - 1;
            float v = 0.f;
            if ((unsigned)yy < (unsigned)H_ && (unsigned)xx < (unsigned)W_)
                v = ib[yy * W_ + xx];
            a[dy][dx] = v;
        }
    float gx = 0.f;
    gx = __fadd_rn(gx, __fmul_rn(-1.f, a[0][0]));
    gx = __fadd_rn(gx, __fmul_rn( 1.f, a[0][2]));
    gx = __fadd_rn(gx, __fmul_rn(-2.f, a[1][0]));
    gx = __fadd_rn(gx, __fmul_rn( 2.f, a[1][2]));
    gx = __fadd_rn(gx, __fmul_rn(-1.f, a[2][0]));
    gx = __fadd_rn(gx, __fmul_rn( 1.f, a[2][2]));
    float gy = 0.f;
    gy = __fadd_rn(gy, __fmul_rn(-1.f, a[0][0]));
    gy = __fadd_rn(gy, __fmul_rn(-2.f, a[0][1]));
    gy = __fadd_rn(gy, __fmul_rn(-1.f, a[0][2]));
    gy = __fadd_rn(gy, __fmul_rn( 1.f, a[2][0]));
    gy = __fadd_rn(gy, __fmul_rn( 2.f, a[2][1]));
    gy = __fadd_rn(gy, __fmul_rn( 1.f, a[2][2]));
    float m = sqrtf(__fadd_rn(__fadd_rn(__fmul_rn(gx, gx), __fmul_rn(gy, gy)), 1e-12f));
    float ang = atan2f(gy, gx);
    const float pi4 = 0.78539816339744830962f;
    int qi = (int)rintf(__fdiv_rn(ang, pi4));
    qi = ((qi % 4) + 4) % 4;
    mag[idx] = m;
    q[idx] = (unsigned char)qi;
}

// NMS -> strong/weak BITMAPS via warp ballot
__global__ void __launch_bounds__(256) nms_kernel(const float* __restrict__ mag,
                                                  const unsigned char* __restrict__ q,
                                                  unsigned* __restrict__ ebits,
                                                  unsigned* __restrict__ wbits) {
    int idx = blockIdx.x * 256 + threadIdx.x;
    if (idx >= NB3) return;
    int p = idx & (NPIX - 1);
    int y = p >> 9;
    int x = p & 511;
    const float* mb = mag + (idx - p);
    float m = mag[idx];
    int qq = q[idx];
    int day, dax, dby, dbx;
    if (qq == 0)      { day = 0;  dax = 1;  dby = 0;  dbx = -1; }
    else if (qq == 1) { day = -1; dax = 1;  dby = 1;  dbx = -1; }
    else if (qq == 2) { day = -1; dax = 0;  dby = 1;  dbx = 0;  }
    else              { day = -1; dax = -1; dby = 1;  dbx = 1;  }
    float na = 0.f, nb = 0.f;
    {
        int yy = y + day, xx = x + dax;
        if ((unsigned)yy < (unsigned)H_ && (unsigned)xx < (unsigned)W_) na = mb[yy * W_ + xx];
        yy = y + dby; xx = x + dbx;
        if ((unsigned)yy < (unsigned)H_ && (unsigned)xx < (unsigned)W_) nb = mb[yy * W_ + xx];
    }
    float nmsv = (m >= na && m >= nb) ? m : 0.f;
    bool strong = (nmsv > 0.2f);
    bool wk = (nmsv > 0.1f && nmsv <= 0.2f);
    unsigned sm_ = __ballot_sync(0xffffffffu, strong);
    unsigned wm_ = __ballot_sync(0xffffffffu, wk);
    if ((threadIdx.x & 31) == 0) {
        ebits[idx >> 5] = sm_;
        wbits[idx >> 5] = wm_;
    }
}

// combined_canny = OR of 3 sigma bitmaps
__global__ void __launch_bounds__(256) combine3_kernel(const unsigned* __restrict__ e,
                                                       float* __restrict__ comb) {
    int idx = blockIdx.x * 256 + threadIdx.x;
    if (idx >= NB) return;
    int w = idx >> 5, bit = idx & 31;
    unsigned v = e[w] | e[(NB >> 5) + w] | e[2 * (NB >> 5) + w];
    comb[idx] = (float)((v >> bit) & 1u);
}

__global__ void __launch_bounds__(256) init_sync_kernel() {
    int i = blockIdx.x * 256 + threadIdx.x;
    if (i < 4) g_swflags[i] = 0;
    if (i == 4) { g_barcnt = 0; g_barphase = 0; }
    if (i < NTILES) {
        g_dirty[0][i] = 1;
        g_dirty[1][i] = 0;
    }
}

__device__ __forceinline__ void grid_barrier(int* phase) {
    __syncthreads();
    if (threadIdx.x == 0) {
        __threadfence();
        int target = *phase + 1;
        if (atomicAdd(&g_barcnt, 1) == (int)gridDim.x - 1) {
            g_barcnt = 0;
            __threadfence();
            atomicExch(&g_barphase, target);
        } else {
            while (atomicAdd(&g_barphase, 0) < target) { __nanosleep(64); }
        }
        __threadfence();
        *phase = target;
    }
    __syncthreads();
}

// ---------------------------------------------------------------------------
// Bitboard hysteresis: one warp per 64x64 tile, rows as uint64 in registers.
// Monotone unique fixpoint -> any schedule converges to the same set.
// ---------------------------------------------------------------------------
__global__ void __launch_bounds__(256) hysteresis_bits() {
    const int lane = threadIdx.x & 31;
    const int wid = threadIdx.x >> 5;
    const int gwarp = blockIdx.x * 8 + wid;
    const int twarps = gridDim.x * 8;
    ull* eb = reinterpret_cast<ull*>(g_ebits);
    const ull* wb = reinterpret_cast<const ull*>(g_wbits);
    int phase = 0;
    for (int it = 0;; it++) {
        const int cur = it & 1, nxt = cur ^ 1;
        if (blockIdx.x == 0 && threadIdx.x == 0)
            ((volatile int*)g_swflags)[(it + 1) & 3] = 0;
        for (int t = gwarp; t < NTILES; t += twarps) {
            if (!((volatile unsigned char*)g_dirty[cur])[t]) continue;
            if (lane == 0) g_dirty[cur][t] = 0;
            const int img = t >> 6, ti = t & 63, ty = ti >> 3, tx = ti & 7;
            const int rbase = (img << 9) + (ty << 6);        // global row of tile top
            const size_t i0 = (size_t)(rbase + 2 * lane) * 8 + tx;
            ull e0 = eb[i0], e1 = eb[i0 + 8];
            ull w0 = wb[i0], w1 = wb[i0 + 8];
            ull L0 = tx > 0 ? eb[i0 - 1] : 0, L1 = tx > 0 ? eb[i0 + 7] : 0;
            ull R0 = tx < 7 ? eb[i0 + 1] : 0, R1 = tx < 7 ? eb[i0 + 9] : 0;
            ull Sm = 0, SB = 0, TmL = 0, TmR = 0, BmL = 0, BmR = 0;
            if (lane == 0 && ty > 0) {
                size_t ih = (size_t)(rbase - 1) * 8 + tx;
                ull Tm = eb[ih];
                TmL = tx > 0 ? eb[ih - 1] : 0;
                TmR = tx < 7 ? eb[ih + 1] : 0;
                Sm = (Tm << 1) | Tm | (Tm >> 1) | ((TmL >> 63) & 1ull) | ((TmR & 1ull) << 63);
            }
            if (lane == 31 && ty < 7) {
                size_t ih = (size_t)(rbase + 64) * 8 + tx;
                ull Bm = eb[ih];
                BmL = tx > 0 ? eb[ih - 1] : 0;
                BmR = tx < 7 ? eb[ih + 1] : 0;
                SB = (Bm << 1) | Bm | (Bm >> 1) | ((BmL >> 63) & 1ull) | ((BmR & 1ull) << 63);
            }
            ull Lp1 = __shfl_up_sync(0xffffffffu, L1, 1); if (lane == 0) Lp1 = TmL;
            ull Rp1 = __shfl_up_sync(0xffffffffu, R1, 1); if (lane == 0) Rp1 = TmR;
            ull Ln0 = __shfl_down_sync(0xffffffffu, L0, 1); if (lane == 31) Ln0 = BmL;
            ull Rn0 = __shfl_down_sync(0xffffffffu, R0, 1); if (lane == 31) Rn0 = BmR;
            const ull Hal0 = (((Lp1 | L0 | L1) >> 63) & 1ull) | (((Rp1 | R0 | R1) & 1ull) << 63);
            const ull Hal1 = (((L0 | L1 | Ln0) >> 63) & 1ull) | (((R0 | R1 | Rn0) & 1ull) << 63);
            const ull oe0 = e0, oe1 = e1;
            for (;;) {
                ull S0 = (e0 << 1) | e0 | (e0 >> 1);
                ull S1 = (e1 << 1) | e1 | (e1 >> 1);
                ull up = __shfl_up_sync(0xffffffffu, S1, 1); if (lane == 0) up = Sm;
                ull dn = __shfl_down_sync(0xffffffffu, S0, 1); if (lane == 31) dn = SB;
                ull n0 = up | S1 | (e0 << 1) | (e0 >> 1) | Hal0;
                ull n1 = S0 | dn | (e1 << 1) | (e1 >> 1) | Hal1;
                ull ne0 = e0 | (w0 & n0);
                ull ne1 = e1 | (w1 & n1);
                bool ch = (ne0 != e0) || (ne1 != e1);
                e0 = ne0; e1 = ne1;
                if (!__ballot_sync(0xffffffffu, ch)) break;
            }
            bool wch = (e0 != oe0) || (e1 != oe1);
            if (__ballot_sync(0xffffffffu, wch)) {
                eb[i0] = e0;
                eb[i0 + 8] = e1;
                if (lane == 0) {
                    ((volatile int*)g_swflags)[it & 3] = 1;
                    for (int dy = -1; dy <= 1; dy++)
                        for (int dx = -1; dx <= 1; dx++) {
                            if (dy == 0 && dx == 0) continue;
                            int ny = ty + dy, nx = tx + dx;
                            if ((unsigned)ny < 8u && (unsigned)nx < 8u)
                                g_dirty[nxt][(t & ~63) | (ny << 3) | nx] = 1;
                        }
                }
            }
        }
        grid_barrier(&phase);
        if (!((volatile int*)g_swflags)[it & 3]) break;
    }
}

// ---------------------------------------------------------------------------
// Conv v3 (unchanged)
// ---------------------------------------------------------------------------
template <int CIN, int COUT, int ACT>
__global__ void __launch_bounds__(256) conv3x3_v3(const float* __restrict__ in,
                                                  const float* __restrict__ wt,
                                                  const float* __restrict__ bias,
                                                  float* __restrict__ out) {
    extern __shared__ float smem[];
    float* s_in = smem;
    float* s_w  = smem + CIN * 34 * 34;
    const int tid = threadIdx.x;
    const int lx = tid & 31, ly = tid >> 5;
    const int b  = blockIdx.z;
    const int x0 = blockIdx.x * 32, y0 = blockIdx.y * 32;

    for (int i = tid; i < CIN * COUT * 12; i += 256) {
        int t  = i % 12;
        int co = (i / 12) % COUT;
        int ci = i / (12 * COUT);
        s_w[i] = (t < 9) ? wt[(co * CIN + ci) * 9 + t] : 0.f;
    }
    const float* inb = in + (size_t)b * CIN * NPIX;
    for (int i = tid; i < CIN * 34 * 34; i += 256) {
        int c  = i / (34 * 34);
        int r  = (i / 34) % 34;
        int cc = i % 34;
        int y = y0 + r - 1, x = x0 + cc - 1;
        float v = 0.f;
        if ((unsigned)y < (unsigned)H_ && (unsigned)x < (unsigned)W_)
            v = inb[(size_t)c * NPIX + y * W_ + x];
        s_in[i] = v;
    }
    __syncthreads();

    constexpr int CH = (COUT >= 8) ? 8 : COUT;
    const int ybase = ly * 4;
    float* ob = out + (size_t)b * COUT * NPIX + (y0 + ybase) * W_ + (x0 + lx);

#pragma unroll
    for (int co0 = 0; co0 < COUT; co0 += CH) {
        ull accA[CH], accB[CH];
#pragma unroll
        for (int j = 0; j < CH; j++) {
            float bv = bias[co0 + j];
            accA[j] = pk2(bv, bv);
            accB[j] = pk2(bv, bv);
        }
#pragma unroll
        for (int ci = 0; ci < CIN; ci++) {
            const float* sc = s_in + ci * (34 * 34);
            ull vA[9], vB[9];
#pragma unroll
            for (int t = 0; t < 9; t++) {
                int dy = t / 3, dx = t % 3;
                float a0 = sc[(ybase + dy) * 34 + lx + dx];
                float a1 = sc[(ybase + dy + 1) * 34 + lx + dx];
                float a2 = sc[(ybase + dy + 2) * 34 + lx + dx];
                float a3 = sc[(ybase + dy + 3) * 34 + lx + dx];
                vA[t] = pk2(a0, a1);
                vB[t] = pk2(a2, a3);
            }
#pragma unroll
            for (int j = 0; j < CH; j++) {
                const float4* wp =
                    reinterpret_cast<const float4*>(&s_w[(ci * COUT + co0 + j) * 12]);
                float4 w0 = wp[0], w1 = wp[1], w2 = wp[2];
                float w[9] = {w0.x, w0.y, w0.z, w0.w, w1.x, w1.y, w1.z, w1.w, w2.x};
#pragma unroll
                for (int t = 0; t < 9; t++) {
                    ull ww = pk2(w[t], w[t]);
                    accA[j] = fma2(vA[t], ww, accA[j]);
                    accB[j] = fma2(vB[t], ww, accB[j]);
                }
            }
        }
#pragma unroll
        for (int j = 0; j < CH; j++) {
            float p0, p1, p2, p3;
            upk2(accA[j], p0, p1);
            upk2(accB[j], p2, p3);
            float pv[4] = {p0, p1, p2, p3};
#pragma unroll
            for (int r = 0; r < 4; r++) {
                float v = pv[r];
                if (ACT == 0) v = (v >= 0.f) ? v : 0.2f * v;
                else v = 1.f / (1.f + expf(-v));
                ob[(size_t)(co0 + j) * NPIX + r * W_] = v;
            }
        }
    }
}

__global__ void __launch_bounds__(256) pack_ce_kernel(const float* __restrict__ comb,
                                                      const float* __restrict__ deep,
                                                      float* __restrict__ ce) {
    int idx = blockIdx.x * 256 + threadIdx.x;
    if (idx >= NB) return;
    int b = idx >> 18;
    int p = idx & (NPIX - 1);
    float* cb = ce + (size_t)b * 2 * NPIX;
    cb[p] = comb[idx];
    cb[NPIX + p] = deep[idx];
}

__global__ void __launch_bounds__(256) final_kernel(const float* __restrict__ refined,
                                                    const float* __restrict__ deep,
                                                    const float* __restrict__ comb,
                                                    const float* __restrict__ mask,
                                                    float* __restrict__ out) {
    int idx = blockIdx.x * 256 + threadIdx.x;
    if (idx >= NB) return;
    int b = idx >> 18;
    int p = idx & (NPIX - 1);
    float r = refined[idx];
    float d = deep[idx];
    float m = mask[idx];
    float c = comb[idx];
    float em = __fadd_rn(__fmul_rn(r, __fadd_rn(1.f, -m)),
                         __fmul_rn(__fmul_rn(d, m), 0.5f));
    const size_t T = (size_t)NB;
    out[idx] = em;
    float* ef = out + T + (size_t)b * 2 * NPIX;
    ef[p] = em;
    ef[NPIX + p] = d;
    out[3 * T + idx] = c;
    out[4 * T + idx] = d;
}

static void gauss5(float sigma, float* k) {
    float kk[5];
    for (int i = 0; i < 5; i++) {
        float r = (float)i - 2.0f;
        float rr = r * r;
        float denom = (float)(2.0 * (double)sigma * (double)sigma);
        float arg = -(rr / denom);
        kk[i] = (float)exp((double)arg);
    }
    float sum = ((((kk[0] + kk[1]) + kk[2]) + kk[3]) + kk[4]);
    for (int i = 0; i < 5; i++) k[i] = kk[i] / sum;
}

template <int CIN, int COUT, int ACT>
static void launch_conv(const float* in, const float* wt, const float* bias, float* out) {
    int smem = (CIN * 34 * 34 + CIN * COUT * 12) * (int)sizeof(float);
    if (smem > 48 * 1024) {
        cudaFuncSetAttribute(conv3x3_v3<CIN, COUT, ACT>,
                             cudaFuncAttributeMaxDynamicSharedMemorySize, smem);
    }
    dim3 grid(W_ / 32, H_ / 32, B_);
    conv3x3_v3<CIN, COUT, ACT><<<grid, 256, smem>>>(in, wt, bias, out);
}

extern "C" void kernel_launch(void* const* d_in, const int* in_sizes, int n_in,
                              void* d_out, int out_size) {
    const float* x    = (const float*)d_in[0];
    const float* mask = (const float*)d_in[1];
    const float* wd1 = (const float*)d_in[2];
    const float* bd1 = (const float*)d_in[3];
    const float* wd2 = (const float*)d_in[4];
    const float* bd2 = (const float*)d_in[5];
    const float* wd3 = (const float*)d_in[6];
    const float* bd3 = (const float*)d_in[7];
    const float* wd4 = (const float*)d_in[8];
    const float* bd4 = (const float*)d_in[9];
    const float* wr1 = (const float*)d_in[10];
    const float* br1 = (const float*)d_in[11];
    const float* wr2 = (const float*)d_in[12];
    const float* br2 = (const float*)d_in[13];
    const float* wr3 = (const float*)d_in[14];
    const float* br3 = (const float*)d_in[15];
    float* out = (float*)d_out;

    float *p_gray, *p_t1, *p_mag, *p_comb, *p_h1, *p_h2, *p_h3;
    float *p_deep, *p_ce, *p_r1, *p_r2, *p_refined, *p_tmp;
    unsigned char *p_q;
    unsigned *p_e, *p_w;
    cudaGetSymbolAddress((void**)&p_gray, g_gray);
    cudaGetSymbolAddress((void**)&p_t1, g_t1);
    cudaGetSymbolAddress((void**)&p_mag, g_mag);
    cudaGetSymbolAddress((void**)&p_comb, g_comb);
    cudaGetSymbolAddress((void**)&p_h1, g_h1);
    cudaGetSymbolAddress((void**)&p_h2, g_h2);
    cudaGetSymbolAddress((void**)&p_h3, g_h3);
    cudaGetSymbolAddress((void**)&p_deep, g_deep);
    cudaGetSymbolAddress((void**)&p_ce, g_ce);
    cudaGetSymbolAddress((void**)&p_r1, g_r1);
    cudaGetSymbolAddress((void**)&p_r2, g_r2);
    cudaGetSymbolAddress((void**)&p_refined, g_refined);
    cudaGetSymbolAddress((void**)&p_q, g_q);
    cudaGetSymbolAddress((void**)&p_e, g_ebits);
    cudaGetSymbolAddress((void**)&p_w, g_wbits);
    cudaGetSymbolAddress((void**)&p_tmp, g_h1);   // reuse conv scratch (16NB >= 3NB)

    const int egrid = NB / 256;
    const int egrid3 = NB3 / 256;
    gray_kernel<<<egrid, 256>>>(x, p_gray);

    K53 kall;
    gauss5(0.5f, kall.k[0]);
    gauss5(1.0f, kall.k[1]);
    gauss5(2.0f, kall.k[2]);
    K5 kint;
    gauss5(1.0f, kint.k);

    int dev = 0;
    cudaGetDevice(&dev);
    int sms = 0;
    cudaDeviceGetAttribute(&sms, cudaDevAttrMultiProcessorCount, dev);
    int per = 0;
    cudaOccupancyMaxActiveBlocksPerMultiprocessor(&per, hysteresis_bits, 256, 0);
    if (per < 1) per = 1;
    if (per > 2) per = 2;
    int hgrid = sms * per;
    if (hgrid > (NTILES + 7) / 8) hgrid = (NTILES + 7) / 8;
    if (hgrid < 1) hgrid = 1;

    dim3 bgrid(W_ / 64, H_ / 16, NIMG);
    blur1_batched<<<bgrid, 256>>>(p_gray, p_tmp, kall);
    blur2_batched<<<bgrid, 256>>>(p_tmp, p_t1, kint);
    magq_kernel<<<egrid3, 256>>>(p_t1, p_mag, p_q);
    nms_kernel<<<egrid3, 256>>>(p_mag, p_q, p_e, p_w);
    init_sync_kernel<<<(NTILES + 255) / 256, 256>>>();
    hysteresis_bits<<<hgrid, 256>>>();
    combine3_kernel<<<egrid, 256>>>(p_e, p_comb);

    launch_conv<3, 16, 0>(x, wd1, bd1, p_h1);
    launch_conv<16, 16, 0>(p_h1, wd2, bd2, p_h2);
    launch_conv<16, 8, 0>(p_h2, wd3, bd3, p_h3);
    launch_conv<8, 1, 1>(p_h3, wd4, bd4, p_deep);

    pack_ce_kernel<<<egrid, 256>>>(p_comb, p_deep, p_ce);
    launch_conv<2, 8, 0>(p_ce, wr1, br1, p_r1);
    launch_conv<8, 4, 0>(p_r1, wr2, br2, p_r2);
    launch_conv<4, 1, 1>(p_r2, wr3, br3, p_refined);

    final_kernel<<<egrid, 256>>>(p_refined, p_deep, p_comb, mask, out);
}